// round 1
// baseline (speedup 1.0000x reference)
#include <cuda_runtime.h>

#define NN   50000
#define NP   50048      // padded row count (multiple of 64)
#define FIN  512
#define HID  128
#define CLS  64
#define NE   800000
#define EPSV 1e-5f

// ---------------- scratch (device globals; no allocation allowed) ----------
__device__ float    g_colsum[FIN];
__device__ float    g_colsq [FIN];
__device__ float    g_mu    [FIN];
__device__ float    g_rstd  [FIN];
__device__ int      g_deg   [NN];
__device__ float    g_dinv  [NN];

__device__ float    g_alpha1[NP];
__device__ unsigned g_xp1   [NP * 16];     // 512 bits per row
__device__ unsigned g_wp1   [HID * 16];
__device__ float    g_beta1 [HID];
__device__ float    g_h1    [NP * HID];
__device__ float    g_agg1  [NN * HID];

__device__ float    g_alpha2[NP];
__device__ unsigned g_xp2   [NP * 4];      // 128 bits per row
__device__ unsigned g_wp2   [CLS * 4];
__device__ float    g_beta2 [CLS];
__device__ float    g_h2    [NP * CLS];

// ---------------- kernels --------------------------------------------------

// zero the accumulators that are atomically built every call; deg starts at 1 (self loop)
__global__ void k_init()
{
    int i = blockIdx.x * 256 + threadIdx.x;
    if (i < FIN) { g_colsum[i] = 0.f; g_colsq[i] = 0.f; }
    if (i < NN)  { g_deg[i] = 1; }
}

// column sums / sum-of-squares for BatchNorm. grid (2, 128), block 256
__global__ void k_colstats(const float* __restrict__ x)
{
    int c  = blockIdx.x * 256 + threadIdx.x;          // 0..511
    int r0 = blockIdx.y * 391;
    int r1 = r0 + 391; if (r1 > NN) r1 = NN;
    float s = 0.f, q = 0.f;
    for (int r = r0; r < r1; ++r) {
        float v = x[r * FIN + c];
        s += v; q += v * v;
    }
    atomicAdd(&g_colsum[c], s);
    atomicAdd(&g_colsq [c], q);
}

__global__ void k_finalize_stats()
{
    int c = threadIdx.x;                               // 512 threads
    float mu  = g_colsum[c] * (1.f / NN);
    float var = g_colsq[c] * (1.f / NN) - mu * mu;
    g_mu[c]   = mu;
    g_rstd[c] = rsqrtf(var + EPSV);
}

__global__ void k_degree(const int* __restrict__ edges)
{
    int e = blockIdx.x * 256 + threadIdx.x;
    if (e < NE) atomicAdd(&g_deg[edges[NE + e]], 1);   // col = target
}

__global__ void k_dinv()
{
    int i = blockIdx.x * 256 + threadIdx.x;
    if (i < NN) g_dinv[i] = rsqrtf((float)g_deg[i]);
}

// per-row: pack sign bits of (x - mu) and alpha = mean(|x-mu|*rstd). block=512
__global__ void k_pack_x1(const float* __restrict__ x)
{
    int m = blockIdx.x;
    int c = threadIdx.x;
    float d  = x[m * FIN + c] - g_mu[c];
    unsigned bal = __ballot_sync(0xffffffffu, d > 0.f);
    int lane = c & 31, w = c >> 5;
    if (lane == 0) g_xp1[m * 16 + w] = bal;
    float ab = fabsf(d) * g_rstd[c];
    #pragma unroll
    for (int o = 16; o > 0; o >>= 1) ab += __shfl_down_sync(0xffffffffu, ab, o);
    __shared__ float ssum[16];
    if (lane == 0) ssum[w] = ab;
    __syncthreads();
    if (threadIdx.x < 16) {
        float s = ssum[threadIdx.x];
        #pragma unroll
        for (int o = 8; o > 0; o >>= 1) s += __shfl_down_sync(0xffffu, s, o);
        if (threadIdx.x == 0) g_alpha1[m] = s * (1.f / FIN);
    }
}

// pack W1 column n: sign bits over k and beta = mean|W1[:,n]|. block=512, grid=128
__global__ void k_pack_w1(const float* __restrict__ W1)
{
    int n = blockIdx.x;
    int k = threadIdx.x;
    float v = W1[k * HID + n];
    unsigned bal = __ballot_sync(0xffffffffu, v > 0.f);
    int lane = k & 31, w = k >> 5;
    if (lane == 0) g_wp1[n * 16 + w] = bal;
    float av = fabsf(v);
    #pragma unroll
    for (int o = 16; o > 0; o >>= 1) av += __shfl_down_sync(0xffffffffu, av, o);
    __shared__ float ssum[16];
    if (lane == 0) ssum[w] = av;
    __syncthreads();
    if (threadIdx.x < 16) {
        float s = ssum[threadIdx.x];
        #pragma unroll
        for (int o = 8; o > 0; o >>= 1) s += __shfl_down_sync(0xffffu, s, o);
        if (threadIdx.x == 0) g_beta1[n] = s * (1.f / FIN);
    }
}

// XNOR-popcount GEMM 1: [NP,512-bit] x [512-bit,128] -> h1. block=128, TM=32 rows
#define TM1 32
__global__ void k_gemm1()
{
    int t  = threadIdx.x;                 // output column 0..127
    int m0 = blockIdx.x * TM1;
    __shared__ unsigned sA[TM1][16];
    __shared__ float    sAl[TM1];
    unsigned w[16];
    #pragma unroll
    for (int i = 0; i < 16; ++i) w[i] = g_wp1[t * 16 + i];
    float beta = g_beta1[t];
    for (int i = t; i < TM1 * 16; i += 128)
        sA[i >> 4][i & 15] = g_xp1[m0 * 16 + i];
    if (t < TM1) sAl[t] = g_alpha1[m0 + t];
    __syncthreads();
    #pragma unroll 4
    for (int m = 0; m < TM1; ++m) {
        int acc = 0;
        #pragma unroll
        for (int i = 0; i < 16; ++i) acc += __popc(w[i] ^ sA[m][i]);
        g_h1[(m0 + m) * HID + t] = sAl[m] * beta * (float)(FIN - 2 * acc);
    }
}

// agg1 = b1 + self-loop term
__global__ void k_init_agg1(const float* __restrict__ b1)
{
    int idx = blockIdx.x * 256 + threadIdx.x;
    if (idx >= NN * HID) return;
    int i = idx >> 7, n = idx & 127;
    float di = g_dinv[i];
    g_agg1[idx] = b1[n] + di * di * g_h1[idx];
}

// edge scatter layer 1: one block per edge, 128 threads
__global__ void k_scatter1(const int* __restrict__ edges)
{
    int e   = blockIdx.x;
    int n   = threadIdx.x;
    int row = __ldg(&edges[e]);
    int col = __ldg(&edges[NE + e]);
    float nrm = g_dinv[row] * g_dinv[col];
    atomicAdd(&g_agg1[col * HID + n], nrm * g_h1[row * HID + n]);
}

// per-row: alpha2 and sign bits of agg1. block=128
__global__ void k_pack_x2()
{
    int m = blockIdx.x;
    int c = threadIdx.x;
    float v = g_agg1[m * HID + c];
    unsigned bal = __ballot_sync(0xffffffffu, v > 0.f);
    int lane = c & 31, w = c >> 5;
    if (lane == 0) g_xp2[m * 4 + w] = bal;
    float av = fabsf(v);
    #pragma unroll
    for (int o = 16; o > 0; o >>= 1) av += __shfl_down_sync(0xffffffffu, av, o);
    __shared__ float ssum[4];
    if (lane == 0) ssum[w] = av;
    __syncthreads();
    if (threadIdx.x < 4) {
        float s = ssum[threadIdx.x];
        #pragma unroll
        for (int o = 2; o > 0; o >>= 1) s += __shfl_down_sync(0xfu, s, o);
        if (threadIdx.x == 0) g_alpha2[m] = s * (1.f / HID);
    }
}

// pack W2 column n. block=128, grid=64
__global__ void k_pack_w2(const float* __restrict__ W2)
{
    int n = blockIdx.x;
    int k = threadIdx.x;
    float v = W2[k * CLS + n];
    unsigned bal = __ballot_sync(0xffffffffu, v > 0.f);
    int lane = k & 31, w = k >> 5;
    if (lane == 0) g_wp2[n * 4 + w] = bal;
    float av = fabsf(v);
    #pragma unroll
    for (int o = 16; o > 0; o >>= 1) av += __shfl_down_sync(0xffffffffu, av, o);
    __shared__ float ssum[4];
    if (lane == 0) ssum[w] = av;
    __syncthreads();
    if (threadIdx.x < 4) {
        float s = ssum[threadIdx.x];
        #pragma unroll
        for (int o = 2; o > 0; o >>= 1) s += __shfl_down_sync(0xfu, s, o);
        if (threadIdx.x == 0) g_beta2[n] = s * (1.f / HID);
    }
}

// XNOR-popcount GEMM 2: block=64 threads, TM=64 rows
#define TM2 64
__global__ void k_gemm2()
{
    int t  = threadIdx.x;                 // 0..63
    int m0 = blockIdx.x * TM2;
    __shared__ unsigned sA[TM2][4];
    __shared__ float    sAl[TM2];
    unsigned w[4];
    #pragma unroll
    for (int i = 0; i < 4; ++i) w[i] = g_wp2[t * 4 + i];
    float beta = g_beta2[t];
    for (int i = t; i < TM2 * 4; i += 64)
        sA[i >> 2][i & 3] = g_xp2[m0 * 4 + i];
    sAl[t] = g_alpha2[m0 + t];
    __syncthreads();
    #pragma unroll 4
    for (int m = 0; m < TM2; ++m) {
        int acc = 0;
        #pragma unroll
        for (int i = 0; i < 4; ++i) acc += __popc(w[i] ^ sA[m][i]);
        g_h2[(m0 + m) * CLS + t] = sAl[m] * beta * (float)(HID - 2 * acc);
    }
}

__global__ void k_init_out(const float* __restrict__ b2, float* __restrict__ out)
{
    int idx = blockIdx.x * 256 + threadIdx.x;
    if (idx >= NN * CLS) return;
    int i = idx >> 6, n = idx & 63;
    float di = g_dinv[i];
    out[idx] = b2[n] + di * di * g_h2[idx];
}

__global__ void k_scatter2(const int* __restrict__ edges, float* __restrict__ out)
{
    int e   = blockIdx.x;
    int n   = threadIdx.x;                // 0..63
    int row = __ldg(&edges[e]);
    int col = __ldg(&edges[NE + e]);
    float nrm = g_dinv[row] * g_dinv[col];
    atomicAdd(&out[col * CLS + n], nrm * g_h2[row * CLS + n]);
}

// log_softmax in place, one warp per row (2 cols per lane). block=128
__global__ void k_logsoftmax(float* __restrict__ out)
{
    int warp = (blockIdx.x * 128 + threadIdx.x) >> 5;
    int lane = threadIdx.x & 31;
    if (warp >= NN) return;
    float* p = out + (size_t)warp * CLS;
    float v0 = p[lane], v1 = p[lane + 32];
    float mx = fmaxf(v0, v1);
    #pragma unroll
    for (int o = 16; o > 0; o >>= 1) mx = fmaxf(mx, __shfl_xor_sync(0xffffffffu, mx, o));
    float s = expf(v0 - mx) + expf(v1 - mx);
    #pragma unroll
    for (int o = 16; o > 0; o >>= 1) s += __shfl_xor_sync(0xffffffffu, s, o);
    float l = mx + logf(s);
    p[lane]      = v0 - l;
    p[lane + 32] = v1 - l;
}

// ---------------- launch ----------------------------------------------------
extern "C" void kernel_launch(void* const* d_in, const int* in_sizes, int n_in,
                              void* d_out, int out_size)
{
    const float* x     = (const float*)d_in[0];
    const int*   edges = (const int*)  d_in[1];
    const float* W1    = (const float*)d_in[2];
    const float* b1    = (const float*)d_in[3];
    const float* W2    = (const float*)d_in[4];
    const float* b2    = (const float*)d_in[5];
    float*       out   = (float*)d_out;

    k_init<<<(NN + 255) / 256, 256>>>();
    { dim3 g(2, 128); k_colstats<<<g, 256>>>(x); }
    k_finalize_stats<<<1, 512>>>();
    k_degree<<<(NE + 255) / 256, 256>>>(edges);
    k_dinv<<<(NN + 255) / 256, 256>>>();

    k_pack_x1<<<NN, 512>>>(x);
    k_pack_w1<<<HID, 512>>>(W1);
    k_gemm1<<<NP / TM1, 128>>>();
    k_init_agg1<<<(NN * HID + 255) / 256, 256>>>(b1);
    k_scatter1<<<NE, HID>>>(edges);

    k_pack_x2<<<NN, 128>>>();
    k_pack_w2<<<CLS, 128>>>(W2);
    k_gemm2<<<NP / TM2, 64>>>();
    k_init_out<<<(NN * CLS + 255) / 256, 256>>>(b2, out);
    k_scatter2<<<NE, CLS>>>(edges, out);

    k_logsoftmax<<<(NN * 32 + 127) / 128, 128>>>(out);
}

// round 2
// speedup vs baseline: 3.4944x; 3.4944x over previous
#include <cuda_runtime.h>

#define NN   50000
#define NP   50176          // padded rows: multiple of 256 (and 64)
#define NBLK 196            // NP / 256
#define FIN  512
#define HID  128
#define CLS  64
#define NE   800000
#define EPSV 1e-5f

// ---------------- scratch (device globals) ----------------------------------
__device__ float    g_colsum[FIN];
__device__ float    g_colsq [FIN];
__device__ float    g_mu    [FIN];
__device__ float    g_rstd  [FIN];
__device__ int      g_cnt   [NP];        // incoming-edge count (no self loop)
__device__ float    g_dinv  [NN];
__device__ int      g_rowstart[NP];
__device__ int      g_cursor  [NN];
__device__ int      g_esrc    [NE];      // CSR: source node per incoming edge
__device__ int      g_partial [NBLK];
__device__ int      g_blkoff  [NBLK];

__device__ float    g_alpha1[NP];
__device__ unsigned g_xp1   [NP * 16];
__device__ unsigned g_wp1   [HID * 16];
__device__ float    g_beta1 [HID];
__device__ float    g_h1    [NP * HID];

__device__ float    g_alpha2[NP];
__device__ unsigned g_xp2   [NP * 4];
__device__ unsigned g_wp2   [CLS * 4];
__device__ float    g_beta2 [CLS];
__device__ float    g_h2    [NP * CLS];

// ---------------- setup kernels ---------------------------------------------
__global__ void k_init()
{
    int i = blockIdx.x * 256 + threadIdx.x;     // grid NBLK*256 = NP
    if (i < FIN) { g_colsum[i] = 0.f; g_colsq[i] = 0.f; }
    g_cnt[i] = 0;
}

__global__ void k_colstats(const float* __restrict__ x)
{
    int c  = blockIdx.x * 256 + threadIdx.x;
    int r0 = blockIdx.y * 391;
    int r1 = r0 + 391; if (r1 > NN) r1 = NN;
    float s = 0.f, q = 0.f;
    for (int r = r0; r < r1; ++r) {
        float v = x[r * FIN + c];
        s += v; q += v * v;
    }
    atomicAdd(&g_colsum[c], s);
    atomicAdd(&g_colsq [c], q);
}

__global__ void k_finalize_stats()
{
    int c = threadIdx.x;
    float mu  = g_colsum[c] * (1.f / NN);
    float var = g_colsq[c] * (1.f / NN) - mu * mu;
    g_mu[c]   = mu;
    g_rstd[c] = rsqrtf(var + EPSV);
}

__global__ void k_cnt(const int* __restrict__ edges)
{
    int e = blockIdx.x * 256 + threadIdx.x;
    if (e < NE) atomicAdd(&g_cnt[edges[NE + e]], 1);
}

__global__ void k_dinv()
{
    int i = blockIdx.x * 256 + threadIdx.x;
    if (i < NN) g_dinv[i] = rsqrtf((float)(g_cnt[i] + 1));
}

// ---------------- CSR build: 3-phase scan + fill -----------------------------
__global__ void k_scanA()
{
    __shared__ int sp[256];
    int t = threadIdx.x, b = blockIdx.x, idx = b * 256 + t;
    int v = g_cnt[idx];
    sp[t] = v; __syncthreads();
    #pragma unroll
    for (int off = 1; off < 256; off <<= 1) {
        int u = (t >= off) ? sp[t - off] : 0;
        __syncthreads();
        sp[t] += u;
        __syncthreads();
    }
    g_rowstart[idx] = sp[t] - v;
    if (t == 255) g_partial[b] = sp[255];
}

__global__ void k_scanB()
{
    __shared__ int sp[256];
    int t = threadIdx.x;
    int v = (t < NBLK) ? g_partial[t] : 0;
    sp[t] = v; __syncthreads();
    #pragma unroll
    for (int off = 1; off < 256; off <<= 1) {
        int u = (t >= off) ? sp[t - off] : 0;
        __syncthreads();
        sp[t] += u;
        __syncthreads();
    }
    if (t < NBLK) g_blkoff[t] = sp[t] - v;
}

__global__ void k_scanC()
{
    int t = threadIdx.x, b = blockIdx.x, idx = b * 256 + t;
    int rs = g_rowstart[idx] + g_blkoff[b];
    g_rowstart[idx] = rs;
    if (idx < NN) g_cursor[idx] = rs;
}

__global__ void k_fill(const int* __restrict__ edges)
{
    int e = blockIdx.x * 256 + threadIdx.x;
    if (e >= NE) return;
    int row = edges[e];
    int col = edges[NE + e];
    int pos = atomicAdd(&g_cursor[col], 1);
    g_esrc[pos] = row;
}

// ---------------- binarize / pack --------------------------------------------
__global__ void k_pack_x1(const float* __restrict__ x)
{
    int m = blockIdx.x;
    int c = threadIdx.x;                         // 512
    float d = x[m * FIN + c] - g_mu[c];
    unsigned bal = __ballot_sync(0xffffffffu, d > 0.f);
    int lane = c & 31, w = c >> 5;
    if (lane == 0) g_xp1[m * 16 + w] = bal;
    float ab = fabsf(d) * g_rstd[c];
    #pragma unroll
    for (int o = 16; o > 0; o >>= 1) ab += __shfl_down_sync(0xffffffffu, ab, o);
    __shared__ float ssum[16];
    if (lane == 0) ssum[w] = ab;
    __syncthreads();
    if (threadIdx.x < 16) {
        float s = ssum[threadIdx.x];
        #pragma unroll
        for (int o = 8; o > 0; o >>= 1) s += __shfl_down_sync(0xffffu, s, o);
        if (threadIdx.x == 0) g_alpha1[m] = s * (1.f / FIN);
    }
}

__global__ void k_pack_w1(const float* __restrict__ W1)
{
    int n = blockIdx.x;
    int k = threadIdx.x;                         // 512
    float v = W1[k * HID + n];
    unsigned bal = __ballot_sync(0xffffffffu, v > 0.f);
    int lane = k & 31, w = k >> 5;
    if (lane == 0) g_wp1[n * 16 + w] = bal;
    float av = fabsf(v);
    #pragma unroll
    for (int o = 16; o > 0; o >>= 1) av += __shfl_down_sync(0xffffffffu, av, o);
    __shared__ float ssum[16];
    if (lane == 0) ssum[w] = av;
    __syncthreads();
    if (threadIdx.x < 16) {
        float s = ssum[threadIdx.x];
        #pragma unroll
        for (int o = 8; o > 0; o >>= 1) s += __shfl_down_sync(0xffffu, s, o);
        if (threadIdx.x == 0) g_beta1[n] = s * (1.f / FIN);
    }
}

__global__ void k_pack_w2(const float* __restrict__ W2)
{
    int n = blockIdx.x;
    int k = threadIdx.x;                         // 128
    float v = W2[k * CLS + n];
    unsigned bal = __ballot_sync(0xffffffffu, v > 0.f);
    int lane = k & 31, w = k >> 5;
    if (lane == 0) g_wp2[n * 4 + w] = bal;
    float av = fabsf(v);
    #pragma unroll
    for (int o = 16; o > 0; o >>= 1) av += __shfl_down_sync(0xffffffffu, av, o);
    __shared__ float ssum[4];
    if (lane == 0) ssum[w] = av;
    __syncthreads();
    if (threadIdx.x < 4) {
        float s = ssum[threadIdx.x];
        #pragma unroll
        for (int o = 2; o > 0; o >>= 1) s += __shfl_down_sync(0xfu, s, o);
        if (threadIdx.x == 0) g_beta2[n] = s * (1.f / HID);
    }
}

// ---------------- XNOR-popcount GEMMs ----------------------------------------
#define TM1 32
__global__ void k_gemm1()
{
    int t  = threadIdx.x;                 // 0..127 (output column)
    int m0 = blockIdx.x * TM1;
    __shared__ unsigned sA[TM1][16];
    __shared__ float    sAl[TM1];
    unsigned w[16];
    #pragma unroll
    for (int i = 0; i < 16; ++i) w[i] = g_wp1[t * 16 + i];
    float beta = g_beta1[t];
    for (int i = t; i < TM1 * 16; i += 128)
        sA[i >> 4][i & 15] = g_xp1[m0 * 16 + i];
    if (t < TM1) sAl[t] = g_alpha1[m0 + t];
    __syncthreads();
    #pragma unroll 4
    for (int m = 0; m < TM1; ++m) {
        int acc = 0;
        #pragma unroll
        for (int i = 0; i < 16; ++i) acc += __popc(w[i] ^ sA[m][i]);
        g_h1[(m0 + m) * HID + t] = sAl[m] * beta * (float)(FIN - 2 * acc);
    }
}

#define TM2 64
__global__ void k_gemm2()
{
    int t  = threadIdx.x;                 // 0..63
    int m0 = blockIdx.x * TM2;
    __shared__ unsigned sA[TM2][4];
    __shared__ float    sAl[TM2];
    unsigned w[4];
    #pragma unroll
    for (int i = 0; i < 4; ++i) w[i] = g_wp2[t * 4 + i];
    float beta = g_beta2[t];
    for (int i = t; i < TM2 * 4; i += 64)
        sA[i >> 2][i & 3] = g_xp2[m0 * 4 + i];
    sAl[t] = g_alpha2[m0 + t];
    __syncthreads();
    #pragma unroll 4
    for (int m = 0; m < TM2; ++m) {
        int acc = 0;
        #pragma unroll
        for (int i = 0; i < 4; ++i) acc += __popc(w[i] ^ sA[m][i]);
        g_h2[(m0 + m) * CLS + t] = sAl[m] * beta * (float)(HID - 2 * acc);
    }
}

// ---------------- CSR gather layer 1 (+ fused BinActive pack) ----------------
__global__ void k_gather1(const float* __restrict__ b1)
{
    int i = blockIdx.x;
    int t = threadIdx.x;                  // 128
    float di = g_dinv[i];
    float acc = b1[t] + di * di * g_h1[i * HID + t];
    int s = g_rowstart[i];
    int e = s + g_cnt[i];
    for (int j = s; j < e; ++j) {
        int r = __ldg(&g_esrc[j]);
        acc += di * __ldg(&g_dinv[r]) * __ldg(&g_h1[r * HID + t]);
    }
    // fused BinActive pack: sign bits + alpha2 = mean |acc|
    unsigned bal = __ballot_sync(0xffffffffu, acc > 0.f);
    int lane = t & 31, w = t >> 5;
    if (lane == 0) g_xp2[i * 4 + w] = bal;
    float av = fabsf(acc);
    #pragma unroll
    for (int o = 16; o > 0; o >>= 1) av += __shfl_down_sync(0xffffffffu, av, o);
    __shared__ float s4[4];
    if (lane == 0) s4[w] = av;
    __syncthreads();
    if (t == 0) g_alpha2[i] = (s4[0] + s4[1] + s4[2] + s4[3]) * (1.f / HID);
}

// ---------------- CSR gather layer 2 (+ fused log_softmax) -------------------
__global__ void k_gather2_lsm(const float* __restrict__ b2, float* __restrict__ out)
{
    int i = blockIdx.x;
    int t = threadIdx.x;                  // 64
    float di = g_dinv[i];
    float acc = b2[t] + di * di * g_h2[i * CLS + t];
    int s = g_rowstart[i];
    int e = s + g_cnt[i];
    for (int j = s; j < e; ++j) {
        int r = __ldg(&g_esrc[j]);
        acc += di * __ldg(&g_dinv[r]) * __ldg(&g_h2[r * CLS + t]);
    }
    // log_softmax over 64 lanes (2 warps)
    int lane = t & 31, w = t >> 5;
    float mx = acc;
    #pragma unroll
    for (int o = 16; o > 0; o >>= 1) mx = fmaxf(mx, __shfl_xor_sync(0xffffffffu, mx, o));
    __shared__ float sm[2], ss[2];
    if (lane == 0) sm[w] = mx;
    __syncthreads();
    mx = fmaxf(sm[0], sm[1]);
    float ex = expf(acc - mx);
    float sum = ex;
    #pragma unroll
    for (int o = 16; o > 0; o >>= 1) sum += __shfl_xor_sync(0xffffffffu, sum, o);
    if (lane == 0) ss[w] = sum;
    __syncthreads();
    sum = ss[0] + ss[1];
    out[i * CLS + t] = acc - mx - logf(sum);
}

// ---------------- launch ------------------------------------------------------
extern "C" void kernel_launch(void* const* d_in, const int* in_sizes, int n_in,
                              void* d_out, int out_size)
{
    const float* x     = (const float*)d_in[0];
    const int*   edges = (const int*)  d_in[1];
    const float* W1    = (const float*)d_in[2];
    const float* b1    = (const float*)d_in[3];
    const float* W2    = (const float*)d_in[4];
    const float* b2    = (const float*)d_in[5];
    float*       out   = (float*)d_out;

    k_init<<<NBLK, 256>>>();
    { dim3 g(2, 128); k_colstats<<<g, 256>>>(x); }
    k_finalize_stats<<<1, 512>>>();
    k_cnt<<<(NE + 255) / 256, 256>>>(edges);
    k_dinv<<<(NN + 255) / 256, 256>>>();

    k_scanA<<<NBLK, 256>>>();
    k_scanB<<<1, 256>>>();
    k_scanC<<<NBLK, 256>>>();
    k_fill<<<(NE + 255) / 256, 256>>>(edges);

    k_pack_x1<<<NN, 512>>>(x);
    k_pack_w1<<<HID, 512>>>(W1);
    k_gemm1<<<NP / TM1, 128>>>();
    k_gather1<<<NN, HID>>>(b1);

    k_pack_w2<<<CLS, 128>>>(W2);
    k_gemm2<<<NP / TM2, 64>>>();
    k_gather2_lsm<<<NN, CLS>>>(b2, out);
}

// round 3
// speedup vs baseline: 3.6005x; 1.0303x over previous
#include <cuda_runtime.h>

#define NN   50000
#define NP   50176          // padded rows: multiple of 256
#define NBLK 196            // NP / 256
#define FIN  512
#define HID  128
#define CLS  64
#define NE   800000
#define EPSV 1e-5f

// ---------------- scratch (device globals; zero at module load) --------------
__device__ float    g_colsum[FIN];     // zeroed by finalize each call
__device__ float    g_colsq [FIN];
__device__ float    g_mu    [FIN];
__device__ float    g_rstd  [FIN];
__device__ int      g_cnt   [NP];      // zeroed by scanC each call
__device__ float    g_dinv  [NP];
__device__ int      g_rowstart[NP];    // exclusive prefix; rowstart[i+1]-rowstart[i] = deg
__device__ int      g_cursor  [NN];
__device__ int      g_esrc    [NE];
__device__ int      g_partial [NBLK];
__device__ int      g_blkoff  [NBLK];

__device__ float    g_alpha1[NP];      // pad rows stay 0 forever
__device__ unsigned g_xp1   [NP * 16];
__device__ unsigned g_wp1   [HID * 16];
__device__ float    g_beta1 [HID];
__device__ float    g_h1    [NP * HID];

__device__ float    g_alpha2[NP];
__device__ unsigned g_xp2   [NP * 4];
__device__ unsigned g_wp2   [CLS * 4];
__device__ float    g_beta2 [CLS];
__device__ float    g_h2    [NP * CLS];

// ---------------- stats ------------------------------------------------------
// grid 400, block 128; each thread owns 4 consecutive columns (float4)
__global__ void k_colstats(const float* __restrict__ x)
{
    int t  = threadIdx.x;
    int r0 = blockIdx.x * 125;
    int r1 = r0 + 125; if (r1 > NN) r1 = NN;
    const float4* xv = (const float4*)x;
    float4 s = make_float4(0.f, 0.f, 0.f, 0.f);
    float4 q = make_float4(0.f, 0.f, 0.f, 0.f);
    for (int r = r0; r < r1; ++r) {
        float4 v = __ldg(&xv[r * 128 + t]);
        s.x += v.x; s.y += v.y; s.z += v.z; s.w += v.w;
        q.x += v.x * v.x; q.y += v.y * v.y; q.z += v.z * v.z; q.w += v.w * v.w;
    }
    int c = t * 4;
    atomicAdd(&g_colsum[c + 0], s.x); atomicAdd(&g_colsum[c + 1], s.y);
    atomicAdd(&g_colsum[c + 2], s.z); atomicAdd(&g_colsum[c + 3], s.w);
    atomicAdd(&g_colsq [c + 0], q.x); atomicAdd(&g_colsq [c + 1], q.y);
    atomicAdd(&g_colsq [c + 2], q.z); atomicAdd(&g_colsq [c + 3], q.w);
}

__global__ void k_finalize_stats()
{
    int c = threadIdx.x;                   // 512
    float su = g_colsum[c], sq = g_colsq[c];
    float mu  = su * (1.f / NN);
    float var = sq * (1.f / NN) - mu * mu;
    g_mu[c]   = mu;
    g_rstd[c] = rsqrtf(var + EPSV);
    g_colsum[c] = 0.f;                     // ready for next replay
    g_colsq [c] = 0.f;
}

__global__ void k_cnt(const int* __restrict__ edges)
{
    int e = blockIdx.x * 256 + threadIdx.x;
    if (e < NE) atomicAdd(&g_cnt[edges[NE + e]], 1);
}

// ---------------- CSR build ---------------------------------------------------
__global__ void k_scanA()
{
    __shared__ int sp[256];
    int t = threadIdx.x, b = blockIdx.x, idx = b * 256 + t;
    int v = g_cnt[idx];
    g_dinv[idx] = rsqrtf((float)(v + 1));   // self loop included
    sp[t] = v; __syncthreads();
    #pragma unroll
    for (int off = 1; off < 256; off <<= 1) {
        int u = (t >= off) ? sp[t - off] : 0;
        __syncthreads();
        sp[t] += u;
        __syncthreads();
    }
    g_rowstart[idx] = sp[t] - v;
    if (t == 255) g_partial[b] = sp[255];
}

__global__ void k_scanB()
{
    __shared__ int sp[256];
    int t = threadIdx.x;
    int v = (t < NBLK) ? g_partial[t] : 0;
    sp[t] = v; __syncthreads();
    #pragma unroll
    for (int off = 1; off < 256; off <<= 1) {
        int u = (t >= off) ? sp[t - off] : 0;
        __syncthreads();
        sp[t] += u;
        __syncthreads();
    }
    if (t < NBLK) g_blkoff[t] = sp[t] - v;
}

__global__ void k_scanC()
{
    int t = threadIdx.x, b = blockIdx.x, idx = b * 256 + t;
    int rs = g_rowstart[idx] + g_blkoff[b];
    g_rowstart[idx] = rs;
    if (idx < NN) g_cursor[idx] = rs;
    g_cnt[idx] = 0;                         // ready for next replay
}

__global__ void k_fill(const int* __restrict__ edges)
{
    int e = blockIdx.x * 256 + threadIdx.x;
    if (e >= NE) return;
    int row = edges[e];
    int col = edges[NE + e];
    int pos = atomicAdd(&g_cursor[col], 1);
    g_esrc[pos] = row;
}

// ---------------- binarize / pack ----------------------------------------------
__global__ void k_pack_x1(const float* __restrict__ x)
{
    int m = blockIdx.x;
    int c = threadIdx.x;                    // 512
    float d = x[m * FIN + c] - g_mu[c];
    unsigned bal = __ballot_sync(0xffffffffu, d > 0.f);
    int lane = c & 31, w = c >> 5;
    if (lane == 0) g_xp1[m * 16 + w] = bal;
    float ab = fabsf(d) * g_rstd[c];
    #pragma unroll
    for (int o = 16; o > 0; o >>= 1) ab += __shfl_down_sync(0xffffffffu, ab, o);
    __shared__ float ssum[16];
    if (lane == 0) ssum[w] = ab;
    __syncthreads();
    if (threadIdx.x < 16) {
        float s = ssum[threadIdx.x];
        #pragma unroll
        for (int o = 8; o > 0; o >>= 1) s += __shfl_down_sync(0xffffu, s, o);
        if (threadIdx.x == 0) g_alpha1[m] = s * (1.f / FIN);
    }
}

__global__ void k_pack_w1(const float* __restrict__ W1)
{
    int n = blockIdx.x;
    int k = threadIdx.x;                    // 512
    float v = W1[k * HID + n];
    unsigned bal = __ballot_sync(0xffffffffu, v > 0.f);
    int lane = k & 31, w = k >> 5;
    if (lane == 0) g_wp1[n * 16 + w] = bal;
    float av = fabsf(v);
    #pragma unroll
    for (int o = 16; o > 0; o >>= 1) av += __shfl_down_sync(0xffffffffu, av, o);
    __shared__ float ssum[16];
    if (lane == 0) ssum[w] = av;
    __syncthreads();
    if (threadIdx.x < 16) {
        float s = ssum[threadIdx.x];
        #pragma unroll
        for (int o = 8; o > 0; o >>= 1) s += __shfl_down_sync(0xffffu, s, o);
        if (threadIdx.x == 0) g_beta1[n] = s * (1.f / FIN);
    }
}

__global__ void k_pack_w2(const float* __restrict__ W2)
{
    int n = blockIdx.x;
    int k = threadIdx.x;                    // 128
    float v = W2[k * CLS + n];
    unsigned bal = __ballot_sync(0xffffffffu, v > 0.f);
    int lane = k & 31, w = k >> 5;
    if (lane == 0) g_wp2[n * 4 + w] = bal;
    float av = fabsf(v);
    #pragma unroll
    for (int o = 16; o > 0; o >>= 1) av += __shfl_down_sync(0xffffffffu, av, o);
    __shared__ float ssum[4];
    if (lane == 0) ssum[w] = av;
    __syncthreads();
    if (threadIdx.x < 4) {
        float s = ssum[threadIdx.x];
        #pragma unroll
        for (int o = 2; o > 0; o >>= 1) s += __shfl_down_sync(0xfu, s, o);
        if (threadIdx.x == 0) g_beta2[n] = s * (1.f / HID);
    }
}

// ---------------- XNOR-popcount GEMMs (dinv folded into epilogue) --------------
#define TM1 32
__global__ void k_gemm1()
{
    int t  = threadIdx.x;                 // 0..127 output col
    int m0 = blockIdx.x * TM1;
    __shared__ unsigned sA[TM1][16];
    __shared__ float    sAl[TM1];
    unsigned w[16];
    #pragma unroll
    for (int i = 0; i < 16; ++i) w[i] = g_wp1[t * 16 + i];
    float beta = g_beta1[t];
    for (int i = t; i < TM1 * 16; i += 128)
        sA[i >> 4][i & 15] = g_xp1[m0 * 16 + i];
    if (t < TM1) sAl[t] = g_alpha1[m0 + t] * g_dinv[m0 + t];
    __syncthreads();
    #pragma unroll 4
    for (int m = 0; m < TM1; ++m) {
        int acc = 0;
        #pragma unroll
        for (int i = 0; i < 16; ++i) acc += __popc(w[i] ^ sA[m][i]);
        g_h1[(m0 + m) * HID + t] = sAl[m] * beta * (float)(FIN - 2 * acc);
    }
}

#define TM2 64
__global__ void k_gemm2()
{
    int t  = threadIdx.x;                 // 0..63
    int m0 = blockIdx.x * TM2;
    __shared__ unsigned sA[TM2][4];
    __shared__ float    sAl[TM2];
    unsigned w[4];
    #pragma unroll
    for (int i = 0; i < 4; ++i) w[i] = g_wp2[t * 4 + i];
    float beta = g_beta2[t];
    for (int i = t; i < TM2 * 4; i += 64)
        sA[i >> 2][i & 3] = g_xp2[m0 * 4 + i];
    sAl[t] = g_alpha2[m0 + t] * g_dinv[m0 + t];
    __syncthreads();
    #pragma unroll 4
    for (int m = 0; m < TM2; ++m) {
        int acc = 0;
        #pragma unroll
        for (int i = 0; i < 4; ++i) acc += __popc(w[i] ^ sA[m][i]);
        g_h2[(m0 + m) * CLS + t] = sAl[m] * beta * (float)(HID - 2 * acc);
    }
}

// ---------------- gather layer 1: 4 warps/node, float4 rows, fused pack --------
__global__ void k_gather1(const float* __restrict__ b1)
{
    int i = blockIdx.x;
    int t = threadIdx.x;                  // 128
    int lane = t & 31, w = t >> 5;
    int s = g_rowstart[i], e = g_rowstart[i + 1];
    const float4* h1v = (const float4*)g_h1;
    float4 acc = make_float4(0.f, 0.f, 0.f, 0.f);
    for (int j = s + w; j < e; j += 4) {
        int r = __ldg(&g_esrc[j]);
        float4 v = __ldg(&h1v[r * 32 + lane]);
        acc.x += v.x; acc.y += v.y; acc.z += v.z; acc.w += v.w;
    }
    __shared__ float sacc[4][HID];
    *(float4*)&sacc[w][lane * 4] = acc;
    __syncthreads();
    float di = g_dinv[i];
    float a = b1[t] + di * (g_h1[i * HID + t]
              + sacc[0][t] + sacc[1][t] + sacc[2][t] + sacc[3][t]);
    // fused BinActive pack
    unsigned bal = __ballot_sync(0xffffffffu, a > 0.f);
    if (lane == 0) g_xp2[i * 4 + w] = bal;
    float av = fabsf(a);
    #pragma unroll
    for (int o = 16; o > 0; o >>= 1) av += __shfl_down_sync(0xffffffffu, av, o);
    __shared__ float s4[4];
    if (lane == 0) s4[w] = av;
    __syncthreads();
    if (t == 0) g_alpha2[i] = (s4[0] + s4[1] + s4[2] + s4[3]) * (1.f / HID);
}

// ---------------- gather layer 2: 4 warps/node, float2 rows, fused lsm --------
__global__ void k_gather2_lsm(const float* __restrict__ b2, float* __restrict__ out)
{
    int i = blockIdx.x;
    int t = threadIdx.x;                  // 128
    int lane = t & 31, w = t >> 5;
    int s = g_rowstart[i], e = g_rowstart[i + 1];
    const float2* h2v = (const float2*)g_h2;
    float2 acc = make_float2(0.f, 0.f);
    for (int j = s + w; j < e; j += 4) {
        int r = __ldg(&g_esrc[j]);
        float2 v = __ldg(&h2v[r * 32 + lane]);
        acc.x += v.x; acc.y += v.y;
    }
    __shared__ float sacc[4][CLS];
    *(float2*)&sacc[w][lane * 2] = acc;
    __syncthreads();
    if (t < CLS) {
        float di = g_dinv[i];
        float a = b2[t] + di * (g_h2[i * CLS + t]
                  + sacc[0][t] + sacc[1][t] + sacc[2][t] + sacc[3][t]);
        // log_softmax across 64 threads (2 warps)
        float mx = a;
        #pragma unroll
        for (int o = 16; o > 0; o >>= 1) mx = fmaxf(mx, __shfl_xor_sync(0xffffffffu, mx, o));
        __shared__ float sm[2], ss[2];
        if (lane == 0) sm[w] = mx;
        __syncwarp();
        // cross-warp combine via smem (both warps in t<64 region)
        __threadfence_block();
        // use a tiny spin-free exchange: both warps write then read after barrier
        // (barrier below covers all 128 threads? t>=64 threads skipped -> use named sync)
        asm volatile("bar.sync 1, 64;");
        mx = fmaxf(sm[0], sm[1]);
        float ex = expf(a - mx);
        float sum = ex;
        #pragma unroll
        for (int o = 16; o > 0; o >>= 1) sum += __shfl_xor_sync(0xffffffffu, sum, o);
        if (lane == 0) ss[w] = sum;
        asm volatile("bar.sync 1, 64;");
        sum = ss[0] + ss[1];
        out[i * CLS + t] = a - mx - logf(sum);
    }
}

// ---------------- launch --------------------------------------------------------
extern "C" void kernel_launch(void* const* d_in, const int* in_sizes, int n_in,
                              void* d_out, int out_size)
{
    const float* x     = (const float*)d_in[0];
    const int*   edges = (const int*)  d_in[1];
    const float* W1    = (const float*)d_in[2];
    const float* b1    = (const float*)d_in[3];
    const float* W2    = (const float*)d_in[4];
    const float* b2    = (const float*)d_in[5];
    float*       out   = (float*)d_out;

    k_cnt<<<(NE + 255) / 256, 256>>>(edges);
    k_colstats<<<400, 128>>>(x);
    k_finalize_stats<<<1, 512>>>();
    k_scanA<<<NBLK, 256>>>();
    k_scanB<<<1, 256>>>();
    k_scanC<<<NBLK, 256>>>();
    k_fill<<<(NE + 255) / 256, 256>>>(edges);

    k_pack_w1<<<HID, 512>>>(W1);
    k_pack_x1<<<NN, 512>>>(x);
    k_gemm1<<<NP / TM1, 128>>>();
    k_gather1<<<NN, HID>>>(b1);

    k_pack_w2<<<CLS, 128>>>(W2);
    k_gemm2<<<NP / TM2, 64>>>();
    k_gather2_lsm<<<NN, 128>>>(b2, out);
}

// round 4
// speedup vs baseline: 3.8231x; 1.0618x over previous
#include <cuda_runtime.h>

#define NN   50000
#define NP   50176          // padded rows: multiple of 256
#define NBLK 196            // NP / 256
#define FIN  512
#define HID  128
#define CLS  64
#define NE   800000
#define EPSV 1e-5f

// ---------------- scratch (device globals) ------------------------------------
__device__ float    g_colsum[FIN];     // zeroed by k_finB each call
__device__ float    g_colsq [FIN];
__device__ float    g_mu    [FIN];
__device__ float    g_rstd  [FIN];
__device__ int      g_cnt   [NP];      // zeroed by scanC each call
__device__ float    g_dinv  [NP];
__device__ int      g_rowstart[NP];
__device__ int      g_cursor  [NN];
__device__ int      g_esrc    [NE];
__device__ int      g_partial [NBLK];
__device__ int      g_blkoff  [NBLK];

__device__ unsigned g_wp1   [HID * 16];
__device__ float    g_beta1 [HID];
__device__ float    g_h1    [NP * HID];

__device__ float    g_alpha2[NP];
__device__ unsigned g_xp2   [NP * 4];
__device__ unsigned g_wp2   [CLS * 4];
__device__ float    g_beta2 [CLS];
__device__ float    g_h2    [NP * CLS];

// ---------------- setup --------------------------------------------------------
__global__ void k_cnt(const int* __restrict__ edges)
{
    int e = blockIdx.x * 256 + threadIdx.x;
    if (e < NE) atomicAdd(&g_cnt[edges[NE + e]], 1);
}

// grid 400, block 128; each thread owns 4 consecutive columns (float4)
__global__ void k_colstats(const float* __restrict__ x)
{
    int t  = threadIdx.x;
    int r0 = blockIdx.x * 125;
    int r1 = r0 + 125; if (r1 > NN) r1 = NN;
    const float4* xv = (const float4*)x;
    float4 s = make_float4(0.f, 0.f, 0.f, 0.f);
    float4 q = make_float4(0.f, 0.f, 0.f, 0.f);
    for (int r = r0; r < r1; ++r) {
        float4 v = __ldg(&xv[r * 128 + t]);
        s.x += v.x; s.y += v.y; s.z += v.z; s.w += v.w;
        q.x += v.x * v.x; q.y += v.y * v.y; q.z += v.z * v.z; q.w += v.w * v.w;
    }
    int c = t * 4;
    atomicAdd(&g_colsum[c + 0], s.x); atomicAdd(&g_colsum[c + 1], s.y);
    atomicAdd(&g_colsum[c + 2], s.z); atomicAdd(&g_colsum[c + 3], s.w);
    atomicAdd(&g_colsq [c + 0], q.x); atomicAdd(&g_colsq [c + 1], q.y);
    atomicAdd(&g_colsq [c + 2], q.z); atomicAdd(&g_colsq [c + 3], q.w);
}

__global__ void k_scanA()
{
    __shared__ int sp[256];
    int t = threadIdx.x, b = blockIdx.x, idx = b * 256 + t;
    int v = g_cnt[idx];
    g_dinv[idx] = rsqrtf((float)(v + 1));
    sp[t] = v; __syncthreads();
    #pragma unroll
    for (int off = 1; off < 256; off <<= 1) {
        int u = (t >= off) ? sp[t - off] : 0;
        __syncthreads();
        sp[t] += u;
        __syncthreads();
    }
    g_rowstart[idx] = sp[t] - v;
    if (t == 255) g_partial[b] = sp[255];
}

// fused: finalize BN stats (512 thr) + scan of block partials (256 thr)
__global__ void k_finB()
{
    int t = threadIdx.x;                   // 512
    float su = g_colsum[t], sq = g_colsq[t];
    float mu  = su * (1.f / NN);
    float var = sq * (1.f / NN) - mu * mu;
    g_mu[t]   = mu;
    g_rstd[t] = rsqrtf(var + EPSV);
    g_colsum[t] = 0.f;
    g_colsq [t] = 0.f;

    __shared__ int sp[256];
    int v = (t < NBLK) ? g_partial[t] : 0;
    if (t < 256) sp[t] = v;
    __syncthreads();
    #pragma unroll
    for (int off = 1; off < 256; off <<= 1) {
        int u = (t >= off && t < 256) ? sp[t - off] : 0;
        __syncthreads();
        if (t < 256) sp[t] += u;
        __syncthreads();
    }
    if (t < NBLK) g_blkoff[t] = sp[t] - v;
}

__global__ void k_scanC()
{
    int t = threadIdx.x, b = blockIdx.x, idx = b * 256 + t;
    int rs = g_rowstart[idx] + g_blkoff[b];
    g_rowstart[idx] = rs;
    if (idx < NN) g_cursor[idx] = rs;
    g_cnt[idx] = 0;                         // ready for next replay
}

__global__ void k_fill(const int* __restrict__ edges)
{
    int e = blockIdx.x * 256 + threadIdx.x;
    if (e >= NE) return;
    int row = edges[e];
    int col = edges[NE + e];
    int pos = atomicAdd(&g_cursor[col], 1);
    g_esrc[pos] = row;
}

// ---------------- fused weight packing (W1 blocks 0..127, W2 blocks 128..191) --
__global__ void k_pack_w(const float* __restrict__ W1, const float* __restrict__ W2)
{
    int b = blockIdx.x;
    int t = threadIdx.x;                    // 512
    int lane = t & 31, w = t >> 5;
    __shared__ float ssum[16];
    if (b < HID) {
        float v = W1[t * HID + b];
        unsigned bal = __ballot_sync(0xffffffffu, v > 0.f);
        if (lane == 0) g_wp1[b * 16 + w] = bal;
        float av = fabsf(v);
        #pragma unroll
        for (int o = 16; o > 0; o >>= 1) av += __shfl_down_sync(0xffffffffu, av, o);
        if (lane == 0) ssum[w] = av;
        __syncthreads();
        if (t < 16) {
            float s = ssum[t];
            #pragma unroll
            for (int o = 8; o > 0; o >>= 1) s += __shfl_down_sync(0xffffu, s, o);
            if (t == 0) g_beta1[b] = s * (1.f / FIN);
        }
    } else {
        int n = b - HID;
        float v = (t < HID) ? W2[t * CLS + n] : 0.f;
        unsigned bal = __ballot_sync(0xffffffffu, v > 0.f);
        if (lane == 0 && w < 4) g_wp2[n * 4 + w] = bal;
        float av = fabsf(v);
        #pragma unroll
        for (int o = 16; o > 0; o >>= 1) av += __shfl_down_sync(0xffffffffu, av, o);
        if (lane == 0) ssum[w] = av;
        __syncthreads();
        if (t == 0)
            g_beta2[n] = (ssum[0] + ssum[1] + ssum[2] + ssum[3]) * (1.f / HID);
    }
}

// ---------------- fused BinActive pack + XNOR-popcount GEMM 1 ------------------
// block 512 thr = 16 warps; each warp packs one row; then 16x128 popc tile.
__global__ void k_pack_gemm1(const float* __restrict__ x)
{
    int t    = threadIdx.x;
    int lane = t & 31, wp = t >> 5;
    int m0   = blockIdx.x * 16;
    int m    = m0 + wp;

    __shared__ unsigned sA[16][16];
    __shared__ float    sAl[16];

    if (m < NN) {
        float ab = 0.f;
        const float* xr = x + (size_t)m * FIN;
        #pragma unroll
        for (int w = 0; w < 16; ++w) {
            int c = w * 32 + lane;
            float d = __ldg(&xr[c]) - g_mu[c];
            unsigned bal = __ballot_sync(0xffffffffu, d > 0.f);
            if (lane == 0) sA[wp][w] = bal;
            ab += fabsf(d) * g_rstd[c];
        }
        #pragma unroll
        for (int o = 16; o > 0; o >>= 1) ab += __shfl_down_sync(0xffffffffu, ab, o);
        if (lane == 0) sAl[wp] = ab * (1.f / FIN) * g_dinv[m];
    } else {
        if (lane < 16) sA[wp][lane] = 0u;
        if (lane == 0) sAl[wp] = 0.f;
    }
    __syncthreads();

    // GEMM: thread t -> col n = t&127, row group rg = t>>7; 4 rows each
    int n  = t & 127;
    int rg = t >> 7;
    unsigned wr[16];
    #pragma unroll
    for (int i = 0; i < 16; ++i) wr[i] = g_wp1[n * 16 + i];
    float bb = g_beta1[n];
    #pragma unroll
    for (int k = 0; k < 4; ++k) {
        int r = rg * 4 + k;
        int acc = 0;
        #pragma unroll
        for (int i = 0; i < 16; ++i) acc += __popc(wr[i] ^ sA[r][i]);
        g_h1[(m0 + r) * HID + n] = sAl[r] * bb * (float)(FIN - 2 * acc);
    }
}

// ---------------- gather 1: smem-staged edge indices, fused BinActive pack -----
__global__ void k_gather1(const float* __restrict__ b1)
{
    int i = blockIdx.x;
    int t = threadIdx.x;                  // 128
    int lane = t & 31, w = t >> 5;
    int s = g_rowstart[i], e = g_rowstart[i + 1];
    const float4* h1v = (const float4*)g_h1;

    __shared__ int   sidx[128];
    __shared__ float sacc[4][HID];
    __shared__ float s4[4];

    float4 acc = make_float4(0.f, 0.f, 0.f, 0.f);
    for (int base = s; base < e; base += 128) {
        int mc = e - base; if (mc > 128) mc = 128;
        if (t < mc) sidx[t] = g_esrc[base + t];
        __syncthreads();
        int k = w;
        for (; k + 4 < mc; k += 8) {
            int r0 = sidx[k], r1 = sidx[k + 4];
            float4 v0 = __ldg(&h1v[r0 * 32 + lane]);
            float4 v1 = __ldg(&h1v[r1 * 32 + lane]);
            acc.x += v0.x + v1.x; acc.y += v0.y + v1.y;
            acc.z += v0.z + v1.z; acc.w += v0.w + v1.w;
        }
        for (; k < mc; k += 4) {
            int r = sidx[k];
            float4 v = __ldg(&h1v[r * 32 + lane]);
            acc.x += v.x; acc.y += v.y; acc.z += v.z; acc.w += v.w;
        }
        __syncthreads();
    }
    *(float4*)&sacc[w][lane * 4] = acc;
    __syncthreads();

    float di = g_dinv[i];
    float a = b1[t] + di * (g_h1[i * HID + t]
              + sacc[0][t] + sacc[1][t] + sacc[2][t] + sacc[3][t]);
    unsigned bal = __ballot_sync(0xffffffffu, a > 0.f);
    if (lane == 0) g_xp2[i * 4 + w] = bal;
    float av = fabsf(a);
    #pragma unroll
    for (int o = 16; o > 0; o >>= 1) av += __shfl_down_sync(0xffffffffu, av, o);
    if (lane == 0) s4[w] = av;
    __syncthreads();
    if (t == 0) g_alpha2[i] = (s4[0] + s4[1] + s4[2] + s4[3]) * (1.f / HID);
}

// ---------------- XNOR-popcount GEMM 2 -----------------------------------------
#define TM2 64
__global__ void k_gemm2()
{
    int t  = threadIdx.x;                 // 0..63
    int m0 = blockIdx.x * TM2;
    __shared__ unsigned sA[TM2][4];
    __shared__ float    sAl[TM2];
    unsigned w[4];
    #pragma unroll
    for (int i = 0; i < 4; ++i) w[i] = g_wp2[t * 4 + i];
    float beta = g_beta2[t];
    for (int i = t; i < TM2 * 4; i += 64)
        sA[i >> 2][i & 3] = g_xp2[m0 * 4 + i];
    sAl[t] = g_alpha2[m0 + t] * g_dinv[m0 + t];
    __syncthreads();
    #pragma unroll 4
    for (int m = 0; m < TM2; ++m) {
        int acc = 0;
        #pragma unroll
        for (int i = 0; i < 4; ++i) acc += __popc(w[i] ^ sA[m][i]);
        g_h2[(m0 + m) * CLS + t] = sAl[m] * beta * (float)(HID - 2 * acc);
    }
}

// ---------------- gather 2: smem-staged indices + fused log_softmax ------------
__global__ void k_gather2_lsm(const float* __restrict__ b2, float* __restrict__ out)
{
    int i = blockIdx.x;
    int t = threadIdx.x;                  // 128
    int lane = t & 31, w = t >> 5;
    int s = g_rowstart[i], e = g_rowstart[i + 1];
    const float2* h2v = (const float2*)g_h2;

    __shared__ int   sidx[128];
    __shared__ float sacc[4][CLS];
    __shared__ float sm[2], ss[2];

    float2 acc = make_float2(0.f, 0.f);
    for (int base = s; base < e; base += 128) {
        int mc = e - base; if (mc > 128) mc = 128;
        if (t < mc) sidx[t] = g_esrc[base + t];
        __syncthreads();
        int k = w;
        for (; k + 4 < mc; k += 8) {
            int r0 = sidx[k], r1 = sidx[k + 4];
            float2 v0 = __ldg(&h2v[r0 * 32 + lane]);
            float2 v1 = __ldg(&h2v[r1 * 32 + lane]);
            acc.x += v0.x + v1.x; acc.y += v0.y + v1.y;
        }
        for (; k < mc; k += 4) {
            int r = sidx[k];
            float2 v = __ldg(&h2v[r * 32 + lane]);
            acc.x += v.x; acc.y += v.y;
        }
        __syncthreads();
    }
    *(float2*)&sacc[w][lane * 2] = acc;
    __syncthreads();

    if (t < CLS) {
        float di = g_dinv[i];
        float a = b2[t] + di * (g_h2[i * CLS + t]
                  + sacc[0][t] + sacc[1][t] + sacc[2][t] + sacc[3][t]);
        float mx = a;
        #pragma unroll
        for (int o = 16; o > 0; o >>= 1) mx = fmaxf(mx, __shfl_xor_sync(0xffffffffu, mx, o));
        if (lane == 0) sm[w] = mx;
        asm volatile("bar.sync 1, 64;");
        mx = fmaxf(sm[0], sm[1]);
        float sum = expf(a - mx);
        #pragma unroll
        for (int o = 16; o > 0; o >>= 1) sum += __shfl_xor_sync(0xffffffffu, sum, o);
        if (lane == 0) ss[w] = sum;
        asm volatile("bar.sync 1, 64;");
        sum = ss[0] + ss[1];
        out[i * CLS + t] = a - mx - logf(sum);
    }
}

// ---------------- launch ---------------------------------------------------------
extern "C" void kernel_launch(void* const* d_in, const int* in_sizes, int n_in,
                              void* d_out, int out_size)
{
    const float* x     = (const float*)d_in[0];
    const int*   edges = (const int*)  d_in[1];
    const float* W1    = (const float*)d_in[2];
    const float* b1    = (const float*)d_in[3];
    const float* W2    = (const float*)d_in[4];
    const float* b2    = (const float*)d_in[5];
    float*       out   = (float*)d_out;

    k_cnt<<<(NE + 255) / 256, 256>>>(edges);
    k_colstats<<<400, 128>>>(x);
    k_scanA<<<NBLK, 256>>>();
    k_finB<<<1, 512>>>();
    k_scanC<<<NBLK, 256>>>();
    k_fill<<<(NE + 255) / 256, 256>>>(edges);

    k_pack_w<<<HID + CLS, 512>>>(W1, W2);
    k_pack_gemm1<<<NP / 16, 512>>>(x);
    k_gather1<<<NN, HID>>>(b1);

    k_gemm2<<<NP / TM2, 64>>>();
    k_gather2_lsm<<<NN, 128>>>(b2, out);
}

// round 5
// speedup vs baseline: 4.6534x; 1.2172x over previous
#include <cuda_runtime.h>

#define NN   50000
#define NP   50176          // padded rows: multiple of 256
#define NBLK 196            // NP / 256
#define FIN  512
#define HID  128
#define CLS  64
#define NE   800000
#define EPSV 1e-5f
#define NFB  1563           // ceil(NE/512)

// ---------------- scratch (device globals) ------------------------------------
__device__ float    g_colsum[FIN];     // zeroed each call by k_scan block 0
__device__ float    g_colsq [FIN];
__device__ float    g_mu    [FIN];
__device__ float    g_rstd  [FIN];
__device__ int      g_cnt   [NP];      // zeroed each call by k_scan
__device__ float    g_dinv  [NP];
__device__ int      g_rowstart[NP];
__device__ int      g_cursor  [NN];
__device__ int      g_esrc    [NE];
__device__ int      g_desc    [NBLK];  // lookback descriptors; reset in kA

__device__ unsigned g_wp1   [HID * 16];
__device__ float    g_beta1 [HID];
__device__ unsigned g_wp2   [CLS * 4];
__device__ float    g_beta2 [CLS];

__device__ short    g_h1d   [NP * HID];   // int16 sign-dot counts, layer 1
__device__ float    g_s1    [NP];         // alpha1 * dinv per row
__device__ short    g_h2d   [NP * CLS];   // int16 counts, layer 2
__device__ float    g_s2    [NP];         // alpha2 * dinv per row

// ================ kA: cnt + colstats + pack_w (block ranges) ==================
__global__ void kA(const int* __restrict__ edges,
                   const float* __restrict__ x,
                   const float* __restrict__ W1,
                   const float* __restrict__ W2)
{
    int b = blockIdx.x;
    int t = threadIdx.x;                 // 512
    int lane = t & 31, w = t >> 5;

    if (b < NFB) {
        // ---- degree count + desc reset ----
        if (b == 0 && t < NBLK) g_desc[t] = 0;
        int e = b * 512 + t;
        if (e < NE) atomicAdd(&g_cnt[edges[NE + e]], 1);
        return;
    }
    if (b < NFB + 400) {
        // ---- column stats: 512 cols, 125 rows per block ----
        int r0 = (b - NFB) * 125;
        int r1 = r0 + 125; if (r1 > NN) r1 = NN;
        float s = 0.f, q = 0.f;
        const float* xc = x + t;
        for (int r = r0; r < r1; ++r) {
            float v = __ldg(&xc[(size_t)r * FIN]);
            s += v; q += v * v;
        }
        atomicAdd(&g_colsum[t], s);
        atomicAdd(&g_colsq [t], q);
        return;
    }
    // ---- weight packing ----
    int bw = b - NFB - 400;              // 0..191
    __shared__ float ssum[16];
    if (bw < HID) {
        float v = W1[t * HID + bw];
        unsigned bal = __ballot_sync(0xffffffffu, v > 0.f);
        if (lane == 0) g_wp1[bw * 16 + w] = bal;
        float av = fabsf(v);
        #pragma unroll
        for (int o = 16; o > 0; o >>= 1) av += __shfl_down_sync(0xffffffffu, av, o);
        if (lane == 0) ssum[w] = av;
        __syncthreads();
        if (t < 16) {
            float s = ssum[t];
            #pragma unroll
            for (int o = 8; o > 0; o >>= 1) s += __shfl_down_sync(0xffffu, s, o);
            if (t == 0) g_beta1[bw] = s * (1.f / FIN);
        }
    } else {
        int n = bw - HID;
        float v = (t < HID) ? W2[t * CLS + n] : 0.f;
        unsigned bal = __ballot_sync(0xffffffffu, v > 0.f);
        if (lane == 0 && w < 4) g_wp2[n * 4 + w] = bal;
        float av = fabsf(v);
        #pragma unroll
        for (int o = 16; o > 0; o >>= 1) av += __shfl_down_sync(0xffffffffu, av, o);
        if (lane == 0) ssum[w] = av;
        __syncthreads();
        if (t == 0)
            g_beta2[n] = (ssum[0] + ssum[1] + ssum[2] + ssum[3]) * (1.f / HID);
    }
}

// ================ kB: single-pass scan (decoupled lookback) + BN finalize =====
__global__ void k_scan()
{
    __shared__ int sp[256];
    __shared__ int spref;
    int t = threadIdx.x, b = blockIdx.x, idx = b * 256 + t;
    int v = g_cnt[idx];
    sp[t] = v; __syncthreads();
    #pragma unroll
    for (int off = 1; off < 256; off <<= 1) {
        int u = (t >= off) ? sp[t - off] : 0;
        __syncthreads();
        sp[t] += u;
        __syncthreads();
    }
    if (t == 255) {
        int inc = sp[255];
        if (b == 0) {
            atomicExch(&g_desc[0], (inc << 2) | 2);
            spref = 0;
        } else {
            atomicExch(&g_desc[b], (inc << 2) | 1);
            int pre = 0, p = b - 1;
            while (true) {
                int d;
                do { d = atomicAdd(&g_desc[p], 0); } while (!(d & 3));
                pre += d >> 2;
                if ((d & 3) == 2) break;
                --p;
            }
            atomicExch(&g_desc[b], ((pre + inc) << 2) | 2);
            spref = pre;
        }
    }
    __syncthreads();
    int rs = sp[t] - v + spref;
    g_rowstart[idx] = rs;
    if (idx < NN) g_cursor[idx] = rs;
    g_dinv[idx] = rsqrtf((float)(v + 1));
    g_cnt[idx]  = 0;                       // ready for next replay
    if (b == 0) {
        #pragma unroll
        for (int k = 0; k < 2; ++k) {
            int c = t + k * 256;
            float su = g_colsum[c], sq = g_colsq[c];
            float mu  = su * (1.f / NN);
            float var = sq * (1.f / NN) - mu * mu;
            g_mu[c]   = mu;
            g_rstd[c] = rsqrtf(var + EPSV);
            g_colsum[c] = 0.f;
            g_colsq [c] = 0.f;
        }
    }
}

// ================ kC: CSR fill + fused BinActive-pack/popc-GEMM1 ===============
__global__ void kC(const int* __restrict__ edges, const float* __restrict__ x)
{
    int b = blockIdx.x;
    int t = threadIdx.x;                 // 512
    if (b < NFB) {
        int e = b * 512 + t;
        if (e >= NE) return;
        int row = edges[e];
        int col = edges[NE + e];
        int pos = atomicAdd(&g_cursor[col], 1);
        g_esrc[pos] = row;
        return;
    }
    // ---- pack + GEMM1: 16 rows per block ----
    int lane = t & 31, wp = t >> 5;
    int m0 = (b - NFB) * 16;
    int m  = m0 + wp;

    __shared__ unsigned sA[16][16];

    if (m < NN) {
        float ab = 0.f;
        const float* xr = x + (size_t)m * FIN;
        #pragma unroll
        for (int w = 0; w < 16; ++w) {
            int c = w * 32 + lane;
            float d = __ldg(&xr[c]) - g_mu[c];
            unsigned bal = __ballot_sync(0xffffffffu, d > 0.f);
            if (lane == 0) sA[wp][w] = bal;
            ab += fabsf(d) * g_rstd[c];
        }
        #pragma unroll
        for (int o = 16; o > 0; o >>= 1) ab += __shfl_down_sync(0xffffffffu, ab, o);
        if (lane == 0) g_s1[m] = ab * (1.f / FIN) * g_dinv[m];
    } else {
        if (lane < 16) sA[wp][lane] = 0u;
    }
    __syncthreads();

    int n  = t & 127;
    int rg = t >> 7;                      // 0..3, 4 rows each
    unsigned wr[16];
    #pragma unroll
    for (int i = 0; i < 16; ++i) wr[i] = g_wp1[n * 16 + i];
    #pragma unroll
    for (int k = 0; k < 4; ++k) {
        int r = rg * 4 + k;
        int acc = 0;
        #pragma unroll
        for (int i = 0; i < 16; ++i) acc += __popc(wr[i] ^ sA[r][i]);
        g_h1d[(m0 + r) * HID + n] = (short)(FIN - 2 * acc);
    }
}

// ================ kD: gather1 (int16 rows) + BinActive + fused GEMM2 ===========
__global__ void k_gather1(const float* __restrict__ b1)
{
    int i = blockIdx.x;
    int t = threadIdx.x;                  // 128
    int lane = t & 31, w = t >> 5;
    int s = g_rowstart[i], e = g_rowstart[i + 1];
    const int2* rows = (const int2*)g_h1d;   // row r: rows[r*32 + lane] = 4 shorts

    __shared__ float    sacc[4][HID];
    __shared__ unsigned sxp[4];
    __shared__ float    s4[4];

    float4 acc = make_float4(0.f, 0.f, 0.f, 0.f);
    if (w == 0) {                          // self-loop term
        float sr = g_s1[i];
        int2 u = __ldg(&rows[i * 32 + lane]);
        acc.x += sr * (float)((short)u.x);
        acc.y += sr * (float)(u.x >> 16);
        acc.z += sr * (float)((short)u.y);
        acc.w += sr * (float)(u.y >> 16);
    }
    int j = s + w;
    int rn = (j < e) ? __ldg(&g_esrc[j]) : 0;
    while (j < e) {
        int r  = rn;
        int jn = j + 4;
        if (jn < e) rn = __ldg(&g_esrc[jn]);
        float sr = __ldg(&g_s1[r]);
        int2 u = __ldg(&rows[r * 32 + lane]);
        acc.x += sr * (float)((short)u.x);
        acc.y += sr * (float)(u.x >> 16);
        acc.z += sr * (float)((short)u.y);
        acc.w += sr * (float)(u.y >> 16);
        j = jn;
    }
    *(float4*)&sacc[w][lane * 4] = acc;
    __syncthreads();

    float di = g_dinv[i];
    float tot = sacc[0][t] + sacc[1][t] + sacc[2][t] + sacc[3][t];
    float a = b1[t] + di * g_beta1[t] * tot;

    unsigned bal = __ballot_sync(0xffffffffu, a > 0.f);
    if (lane == 0) sxp[w] = bal;
    float av = fabsf(a);
    #pragma unroll
    for (int o = 16; o > 0; o >>= 1) av += __shfl_down_sync(0xffffffffu, av, o);
    if (lane == 0) s4[w] = av;
    __syncthreads();

    if (t == 0) g_s2[i] = (s4[0] + s4[1] + s4[2] + s4[3]) * (1.f / HID) * di;
    if (t < CLS) {
        uint4 wv = __ldg((const uint4*)&g_wp2[t * 4]);
        int acc2 = __popc(wv.x ^ sxp[0]) + __popc(wv.y ^ sxp[1])
                 + __popc(wv.z ^ sxp[2]) + __popc(wv.w ^ sxp[3]);
        g_h2d[i * CLS + t] = (short)(HID - 2 * acc2);
    }
}

// ================ kF: gather2 (int16 rows) + fused log_softmax =================
__global__ void k_gather2_lsm(const float* __restrict__ b2, float* __restrict__ out)
{
    int i = blockIdx.x;
    int t = threadIdx.x;                  // 128
    int lane = t & 31, w = t >> 5;
    int s = g_rowstart[i], e = g_rowstart[i + 1];
    const int* rows = (const int*)g_h2d;  // row r: rows[r*32 + lane] = 2 shorts

    __shared__ float sacc[4][CLS];
    __shared__ float sm[2], ss[2];

    float2 acc = make_float2(0.f, 0.f);
    if (w == 0) {
        float sr = g_s2[i];
        int u = __ldg(&rows[i * 32 + lane]);
        acc.x += sr * (float)((short)u);
        acc.y += sr * (float)(u >> 16);
    }
    int j = s + w;
    int rn = (j < e) ? __ldg(&g_esrc[j]) : 0;
    while (j < e) {
        int r  = rn;
        int jn = j + 4;
        if (jn < e) rn = __ldg(&g_esrc[jn]);
        float sr = __ldg(&g_s2[r]);
        int u = __ldg(&rows[r * 32 + lane]);
        acc.x += sr * (float)((short)u);
        acc.y += sr * (float)(u >> 16);
        j = jn;
    }
    *(float2*)&sacc[w][lane * 2] = acc;
    __syncthreads();

    if (t < CLS) {
        float di = g_dinv[i];
        float tot = sacc[0][t] + sacc[1][t] + sacc[2][t] + sacc[3][t];
        float a = b2[t] + di * g_beta2[t] * tot;

        float mx = a;
        #pragma unroll
        for (int o = 16; o > 0; o >>= 1) mx = fmaxf(mx, __shfl_xor_sync(0xffffffffu, mx, o));
        if (lane == 0) sm[w] = mx;
        asm volatile("bar.sync 1, 64;");
        mx = fmaxf(sm[0], sm[1]);
        float sum = expf(a - mx);
        #pragma unroll
        for (int o = 16; o > 0; o >>= 1) sum += __shfl_xor_sync(0xffffffffu, sum, o);
        if (lane == 0) ss[w] = sum;
        asm volatile("bar.sync 1, 64;");
        sum = ss[0] + ss[1];
        out[i * CLS + t] = a - mx - logf(sum);
    }
}

// ---------------- launch ---------------------------------------------------------
extern "C" void kernel_launch(void* const* d_in, const int* in_sizes, int n_in,
                              void* d_out, int out_size)
{
    const float* x     = (const float*)d_in[0];
    const int*   edges = (const int*)  d_in[1];
    const float* W1    = (const float*)d_in[2];
    const float* b1    = (const float*)d_in[3];
    const float* W2    = (const float*)d_in[4];
    const float* b2    = (const float*)d_in[5];
    float*       out   = (float*)d_out;

    kA<<<NFB + 400 + 192, 512>>>(edges, x, W1, W2);
    k_scan<<<NBLK, 256>>>();
    kC<<<NFB + NP / 16, 512>>>(edges, x);
    k_gather1<<<NN, 128>>>(b1);
    k_gather2_lsm<<<NN, 128>>>(b2, out);
}

// round 6
// speedup vs baseline: 5.5183x; 1.1859x over previous
#include <cuda_runtime.h>

#define NN   50000
#define NP   50176          // padded rows: multiple of 256
#define NBLK 196            // NP / 256
#define FIN  512
#define HID  128
#define CLS  64
#define NE   800000
#define EPSV 1e-5f
#define NFB  1563           // ceil(NE/512)

// ---------------- scratch (device globals) ------------------------------------
__device__ float    g_colsum[FIN];     // zeroed each call by k_scan block 0
__device__ float    g_colsq [FIN];
__device__ float    g_mu    [FIN];
__device__ float    g_rstd  [FIN];
__device__ int      g_cnt   [NP];      // zeroed each call by k_scan
__device__ float    g_dinv  [NP];
__device__ int      g_rowstart[NP];
__device__ int      g_cursor  [NN];
__device__ int      g_esrc    [NE];
__device__ int      g_desc    [NBLK];  // lookback descriptors; reset in kA

__device__ unsigned g_wp1   [HID * 16];
__device__ float    g_beta1 [HID];
__device__ unsigned g_wp2   [CLS * 4];   // permuted: word w bit l = sign W2[4l+w, n]
__device__ float    g_beta2 [CLS];

__device__ short    g_h1d   [NP * HID];   // int16 sign-dot counts, layer 1
__device__ float    g_s1    [NP];         // alpha1 * dinv per row
__device__ short    g_h2d   [NP * CLS];   // int16 counts, layer 2
__device__ float    g_s2    [NP];         // alpha2 * dinv per row

// ================ kA: cnt + colstats + pack_w (block ranges) ==================
__global__ void kA(const int* __restrict__ edges,
                   const float* __restrict__ x,
                   const float* __restrict__ W1,
                   const float* __restrict__ W2)
{
    int b = blockIdx.x;
    int t = threadIdx.x;                 // 512
    int lane = t & 31, w = t >> 5;

    if (b < NFB) {
        if (b == 0 && t < NBLK) g_desc[t] = 0;
        int e = b * 512 + t;
        if (e < NE) atomicAdd(&g_cnt[edges[NE + e]], 1);
        return;
    }
    if (b < NFB + 400) {
        int r0 = (b - NFB) * 125;
        int r1 = r0 + 125; if (r1 > NN) r1 = NN;
        float s = 0.f, q = 0.f;
        const float* xc = x + t;
        for (int r = r0; r < r1; ++r) {
            float v = __ldg(&xc[(size_t)r * FIN]);
            s += v; q += v * v;
        }
        atomicAdd(&g_colsum[t], s);
        atomicAdd(&g_colsq [t], q);
        return;
    }
    int bw = b - NFB - 400;              // 0..191
    __shared__ float ssum[16];
    if (bw < HID) {
        float v = W1[t * HID + bw];
        unsigned bal = __ballot_sync(0xffffffffu, v > 0.f);
        if (lane == 0) g_wp1[bw * 16 + w] = bal;
        float av = fabsf(v);
        #pragma unroll
        for (int o = 16; o > 0; o >>= 1) av += __shfl_down_sync(0xffffffffu, av, o);
        if (lane == 0) ssum[w] = av;
        __syncthreads();
        if (t < 16) {
            float s = ssum[t];
            #pragma unroll
            for (int o = 8; o > 0; o >>= 1) s += __shfl_down_sync(0xffffu, s, o);
            if (t == 0) g_beta1[bw] = s * (1.f / FIN);
        }
    } else {
        int n = bw - HID;
        // permuted packing: thread t<128, word w = t>>5 (0..3), row = 4*lane + w
        float v = (t < HID) ? W2[(4 * lane + w) * CLS + n] : 0.f;
        unsigned bal = __ballot_sync(0xffffffffu, v > 0.f);
        if (lane == 0 && w < 4) g_wp2[n * 4 + w] = bal;
        float av = fabsf(v);
        #pragma unroll
        for (int o = 16; o > 0; o >>= 1) av += __shfl_down_sync(0xffffffffu, av, o);
        if (lane == 0) ssum[w] = av;
        __syncthreads();
        if (t == 0)
            g_beta2[n] = (ssum[0] + ssum[1] + ssum[2] + ssum[3]) * (1.f / HID);
    }
}

// ================ kB: single-pass scan (decoupled lookback) + BN finalize =====
__global__ void k_scan()
{
    __shared__ int sp[256];
    __shared__ int spref;
    int t = threadIdx.x, b = blockIdx.x, idx = b * 256 + t;
    int v = g_cnt[idx];
    sp[t] = v; __syncthreads();
    #pragma unroll
    for (int off = 1; off < 256; off <<= 1) {
        int u = (t >= off) ? sp[t - off] : 0;
        __syncthreads();
        sp[t] += u;
        __syncthreads();
    }
    if (t == 255) {
        int inc = sp[255];
        if (b == 0) {
            atomicExch(&g_desc[0], (inc << 2) | 2);
            spref = 0;
        } else {
            atomicExch(&g_desc[b], (inc << 2) | 1);
            int pre = 0, p = b - 1;
            while (true) {
                int d;
                do { d = atomicAdd(&g_desc[p], 0); } while (!(d & 3));
                pre += d >> 2;
                if ((d & 3) == 2) break;
                --p;
            }
            atomicExch(&g_desc[b], ((pre + inc) << 2) | 2);
            spref = pre;
        }
    }
    __syncthreads();
    int rs = sp[t] - v + spref;
    g_rowstart[idx] = rs;
    if (idx < NN) g_cursor[idx] = rs;
    g_dinv[idx] = rsqrtf((float)(v + 1));
    g_cnt[idx]  = 0;
    if (b == 0) {
        #pragma unroll
        for (int k = 0; k < 2; ++k) {
            int c = t + k * 256;
            float su = g_colsum[c], sq = g_colsq[c];
            float mu  = su * (1.f / NN);
            float var = sq * (1.f / NN) - mu * mu;
            g_mu[c]   = mu;
            g_rstd[c] = rsqrtf(var + EPSV);
            g_colsum[c] = 0.f;
            g_colsq [c] = 0.f;
        }
    }
}

// ================ kC: CSR fill + fused BinActive-pack/popc-GEMM1 ===============
__global__ void kC(const int* __restrict__ edges, const float* __restrict__ x)
{
    int b = blockIdx.x;
    int t = threadIdx.x;                 // 512
    if (b < NFB) {
        int e = b * 512 + t;
        if (e >= NE) return;
        int row = edges[e];
        int col = edges[NE + e];
        int pos = atomicAdd(&g_cursor[col], 1);
        g_esrc[pos] = row;
        return;
    }
    int lane = t & 31, wp = t >> 5;
    int m0 = (b - NFB) * 16;
    int m  = m0 + wp;

    __shared__ unsigned sA[16][16];

    if (m < NN) {
        float ab = 0.f;
        const float* xr = x + (size_t)m * FIN;
        #pragma unroll
        for (int w = 0; w < 16; ++w) {
            int c = w * 32 + lane;
            float d = __ldg(&xr[c]) - g_mu[c];
            unsigned bal = __ballot_sync(0xffffffffu, d > 0.f);
            if (lane == 0) sA[wp][w] = bal;
            ab += fabsf(d) * g_rstd[c];
        }
        #pragma unroll
        for (int o = 16; o > 0; o >>= 1) ab += __shfl_down_sync(0xffffffffu, ab, o);
        if (lane == 0) g_s1[m] = ab * (1.f / FIN) * g_dinv[m];
    } else {
        if (lane < 16) sA[wp][lane] = 0u;
    }
    __syncthreads();

    int n  = t & 127;
    int rg = t >> 7;                      // 0..3, 4 rows each
    unsigned wr[16];
    #pragma unroll
    for (int i = 0; i < 16; ++i) wr[i] = g_wp1[n * 16 + i];
    #pragma unroll
    for (int k = 0; k < 4; ++k) {
        int r = rg * 4 + k;
        int acc = 0;
        #pragma unroll
        for (int i = 0; i < 16; ++i) acc += __popc(wr[i] ^ sA[r][i]);
        g_h1d[(m0 + r) * HID + n] = (short)(FIN - 2 * acc);
    }
}

// ================ gather1: warp-per-node, fused BinActive + GEMM2 ==============
// 256 thr = 8 warps = 8 nodes per block. Lane l owns cols 4l..4l+3.
__global__ void k_gather1(const float* __restrict__ b1)
{
    int lane = threadIdx.x & 31;
    int i = blockIdx.x * 8 + (threadIdx.x >> 5);
    const int2* rows = (const int2*)g_h1d;

    float4 acc;
    {   // self loop
        float sr = __ldg(&g_s1[i]);
        int2 u = __ldg(&rows[i * 32 + lane]);
        acc.x = sr * (float)((short)u.x);
        acc.y = sr * (float)(u.x >> 16);
        acc.z = sr * (float)((short)u.y);
        acc.w = sr * (float)(u.y >> 16);
    }
    int s = g_rowstart[i], e = g_rowstart[i + 1];
    for (int base = s; base < e; base += 32) {
        int cnt = e - base; if (cnt > 32) cnt = 32;
        int idx = 0; float sv = 0.f;
        if (lane < cnt) { idx = __ldg(&g_esrc[base + lane]); sv = __ldg(&g_s1[idx]); }
        int k = 0;
        for (; k + 1 < cnt; k += 2) {
            int   r0 = __shfl_sync(0xffffffffu, idx, k);
            int   r1 = __shfl_sync(0xffffffffu, idx, k + 1);
            float q0 = __shfl_sync(0xffffffffu, sv, k);
            float q1 = __shfl_sync(0xffffffffu, sv, k + 1);
            int2 u0 = __ldg(&rows[r0 * 32 + lane]);
            int2 u1 = __ldg(&rows[r1 * 32 + lane]);
            acc.x += q0 * (float)((short)u0.x) + q1 * (float)((short)u1.x);
            acc.y += q0 * (float)(u0.x >> 16)  + q1 * (float)(u1.x >> 16);
            acc.z += q0 * (float)((short)u0.y) + q1 * (float)((short)u1.y);
            acc.w += q0 * (float)(u0.y >> 16)  + q1 * (float)(u1.y >> 16);
        }
        if (k < cnt) {
            int   r0 = __shfl_sync(0xffffffffu, idx, k);
            float q0 = __shfl_sync(0xffffffffu, sv, k);
            int2 u0 = __ldg(&rows[r0 * 32 + lane]);
            acc.x += q0 * (float)((short)u0.x);
            acc.y += q0 * (float)(u0.x >> 16);
            acc.z += q0 * (float)((short)u0.y);
            acc.w += q0 * (float)(u0.y >> 16);
        }
    }

    float di = g_dinv[i];
    float4 bb = __ldg((const float4*)&b1[lane * 4]);
    float4 be = *(const float4*)&g_beta1[lane * 4];
    float a0 = bb.x + di * be.x * acc.x;
    float a1 = bb.y + di * be.y * acc.y;
    float a2 = bb.z + di * be.z * acc.z;
    float a3 = bb.w + di * be.w * acc.w;

    float av = fabsf(a0) + fabsf(a1) + fabsf(a2) + fabsf(a3);
    #pragma unroll
    for (int o = 16; o > 0; o >>= 1) av += __shfl_xor_sync(0xffffffffu, av, o);
    if (lane == 0) g_s2[i] = av * (1.f / HID) * di;

    unsigned x0 = __ballot_sync(0xffffffffu, a0 > 0.f);
    unsigned x1 = __ballot_sync(0xffffffffu, a1 > 0.f);
    unsigned x2 = __ballot_sync(0xffffffffu, a2 > 0.f);
    unsigned x3 = __ballot_sync(0xffffffffu, a3 > 0.f);

    uint4 wA = *(const uint4*)&g_wp2[lane * 4];
    uint4 wB = *(const uint4*)&g_wp2[(lane + 32) * 4];
    int d1 = HID - 2 * (__popc(wA.x ^ x0) + __popc(wA.y ^ x1)
                      + __popc(wA.z ^ x2) + __popc(wA.w ^ x3));
    int d2 = HID - 2 * (__popc(wB.x ^ x0) + __popc(wB.y ^ x1)
                      + __popc(wB.z ^ x2) + __popc(wB.w ^ x3));
    g_h2d[i * CLS + lane]      = (short)d1;
    g_h2d[i * CLS + lane + 32] = (short)d2;
}

// ================ gather2: warp-per-node + fused log_softmax ===================
// Lane l owns cols 2l, 2l+1.
__global__ void k_gather2_lsm(const float* __restrict__ b2, float* __restrict__ out)
{
    int lane = threadIdx.x & 31;
    int i = blockIdx.x * 8 + (threadIdx.x >> 5);
    const int* rows = (const int*)g_h2d;

    float2 acc;
    {
        float sr = __ldg(&g_s2[i]);
        int u = __ldg(&rows[i * 32 + lane]);
        acc.x = sr * (float)((short)u);
        acc.y = sr * (float)(u >> 16);
    }
    int s = g_rowstart[i], e = g_rowstart[i + 1];
    for (int base = s; base < e; base += 32) {
        int cnt = e - base; if (cnt > 32) cnt = 32;
        int idx = 0; float sv = 0.f;
        if (lane < cnt) { idx = __ldg(&g_esrc[base + lane]); sv = __ldg(&g_s2[idx]); }
        int k = 0;
        for (; k + 1 < cnt; k += 2) {
            int   r0 = __shfl_sync(0xffffffffu, idx, k);
            int   r1 = __shfl_sync(0xffffffffu, idx, k + 1);
            float q0 = __shfl_sync(0xffffffffu, sv, k);
            float q1 = __shfl_sync(0xffffffffu, sv, k + 1);
            int u0 = __ldg(&rows[r0 * 32 + lane]);
            int u1 = __ldg(&rows[r1 * 32 + lane]);
            acc.x += q0 * (float)((short)u0) + q1 * (float)((short)u1);
            acc.y += q0 * (float)(u0 >> 16)  + q1 * (float)(u1 >> 16);
        }
        if (k < cnt) {
            int   r0 = __shfl_sync(0xffffffffu, idx, k);
            float q0 = __shfl_sync(0xffffffffu, sv, k);
            int u0 = __ldg(&rows[r0 * 32 + lane]);
            acc.x += q0 * (float)((short)u0);
            acc.y += q0 * (float)(u0 >> 16);
        }
    }

    float di = g_dinv[i];
    float2 bb = __ldg((const float2*)&b2[lane * 2]);
    float2 be = *(const float2*)&g_beta2[lane * 2];
    float a0 = bb.x + di * be.x * acc.x;
    float a1 = bb.y + di * be.y * acc.y;

    float mx = fmaxf(a0, a1);
    #pragma unroll
    for (int o = 16; o > 0; o >>= 1) mx = fmaxf(mx, __shfl_xor_sync(0xffffffffu, mx, o));
    float sum = expf(a0 - mx) + expf(a1 - mx);
    #pragma unroll
    for (int o = 16; o > 0; o >>= 1) sum += __shfl_xor_sync(0xffffffffu, sum, o);
    float l = mx + logf(sum);
    ((float2*)out)[i * 32 + lane] = make_float2(a0 - l, a1 - l);
}

// ---------------- launch ---------------------------------------------------------
extern "C" void kernel_launch(void* const* d_in, const int* in_sizes, int n_in,
                              void* d_out, int out_size)
{
    const float* x     = (const float*)d_in[0];
    const int*   edges = (const int*)  d_in[1];
    const float* W1    = (const float*)d_in[2];
    const float* b1    = (const float*)d_in[3];
    const float* W2    = (const float*)d_in[4];
    const float* b2    = (const float*)d_in[5];
    float*       out   = (float*)d_out;

    kA<<<NFB + 400 + 192, 512>>>(edges, x, W1, W2);
    k_scan<<<NBLK, 256>>>();
    kC<<<NFB + NP / 16, 512>>>(edges, x);
    k_gather1<<<NN / 8, 256>>>(b1);
    k_gather2_lsm<<<NN / 8, 256>>>(b2, out);
}

// round 7
// speedup vs baseline: 5.6007x; 1.0149x over previous
#include <cuda_runtime.h>
#include <cuda_bf16.h>

#define NN   50000
#define NP   50176          // padded rows: multiple of 256
#define NBLK 196            // NP / 256
#define FIN  512
#define HID  128
#define CLS  64
#define NE   800000
#define EPSV 1e-5f
#define NFB  1563           // ceil(NE/512)

// ---------------- scratch (device globals) ------------------------------------
__device__ float    g_colsum[FIN];     // zeroed each call by k_scan block 0
__device__ float    g_colsq [FIN];
__device__ float    g_mu    [FIN];
__device__ float    g_rstd  [FIN];
__device__ int      g_cnt   [NP];      // zeroed each call by k_scan
__device__ float    g_dinv  [NP];
__device__ int      g_rowstart[NP];
__device__ int      g_cursor  [NN];
__device__ int      g_esrc    [NE];
__device__ int      g_desc    [NBLK];  // lookback descriptors; reset in kA

__device__ unsigned g_wp1   [HID * 16];
__device__ float    g_beta1 [HID];
__device__ unsigned g_wp2   [CLS * 4];   // permuted: word w bit l = sign W2[4l+w, n]
__device__ float    g_beta2 [CLS];

__device__ unsigned short g_h1b [NP * HID];   // bf16 sign-dot counts (exact: even ints <=512)
__device__ float          g_s1  [NP];         // alpha1 * dinv per row
__device__ unsigned       g_h2b [NP * CLS / 2]; // bf16x2 counts, layer 2
__device__ float          g_s2  [NP];

__device__ __forceinline__ float bflo(unsigned w) { return __uint_as_float(w << 16); }
__device__ __forceinline__ float bfhi(unsigned w) { return __uint_as_float(w & 0xffff0000u); }

// ================ kA: cnt + colstats + pack_w (block ranges) ==================
__global__ void kA(const int* __restrict__ edges,
                   const float* __restrict__ x,
                   const float* __restrict__ W1,
                   const float* __restrict__ W2)
{
    int b = blockIdx.x;
    int t = threadIdx.x;                 // 512
    int lane = t & 31, w = t >> 5;

    if (b < NFB) {
        if (b == 0 && t < NBLK) g_desc[t] = 0;
        int e = b * 512 + t;
        if (e < NE) atomicAdd(&g_cnt[edges[NE + e]], 1);
        return;
    }
    if (b < NFB + 400) {
        int r0 = (b - NFB) * 125;
        int r1 = r0 + 125; if (r1 > NN) r1 = NN;
        float s = 0.f, q = 0.f;
        const float* xc = x + t;
        for (int r = r0; r < r1; ++r) {
            float v = __ldg(&xc[(size_t)r * FIN]);
            s += v; q += v * v;
        }
        atomicAdd(&g_colsum[t], s);
        atomicAdd(&g_colsq [t], q);
        return;
    }
    int bw = b - NFB - 400;              // 0..191
    __shared__ float ssum[16];
    if (bw < HID) {
        float v = W1[t * HID + bw];
        unsigned bal = __ballot_sync(0xffffffffu, v > 0.f);
        if (lane == 0) g_wp1[bw * 16 + w] = bal;
        float av = fabsf(v);
        #pragma unroll
        for (int o = 16; o > 0; o >>= 1) av += __shfl_down_sync(0xffffffffu, av, o);
        if (lane == 0) ssum[w] = av;
        __syncthreads();
        if (t < 16) {
            float s = ssum[t];
            #pragma unroll
            for (int o = 8; o > 0; o >>= 1) s += __shfl_down_sync(0xffffu, s, o);
            if (t == 0) g_beta1[bw] = s * (1.f / FIN);
        }
    } else {
        int n = bw - HID;
        // permuted packing: word w bit l = sign of W2[4l+w, n]
        float v = (t < HID) ? W2[(4 * lane + w) * CLS + n] : 0.f;
        unsigned bal = __ballot_sync(0xffffffffu, v > 0.f);
        if (lane == 0 && w < 4) g_wp2[n * 4 + w] = bal;
        float av = fabsf(v);
        #pragma unroll
        for (int o = 16; o > 0; o >>= 1) av += __shfl_down_sync(0xffffffffu, av, o);
        if (lane == 0) ssum[w] = av;
        __syncthreads();
        if (t == 0)
            g_beta2[n] = (ssum[0] + ssum[1] + ssum[2] + ssum[3]) * (1.f / HID);
    }
}

// ================ kB: single-pass scan (decoupled lookback) + BN finalize =====
__global__ void k_scan()
{
    __shared__ int sp[256];
    __shared__ int spref;
    int t = threadIdx.x, b = blockIdx.x, idx = b * 256 + t;
    int v = g_cnt[idx];
    sp[t] = v; __syncthreads();
    #pragma unroll
    for (int off = 1; off < 256; off <<= 1) {
        int u = (t >= off) ? sp[t - off] : 0;
        __syncthreads();
        sp[t] += u;
        __syncthreads();
    }
    if (t == 255) {
        int inc = sp[255];
        if (b == 0) {
            atomicExch(&g_desc[0], (inc << 2) | 2);
            spref = 0;
        } else {
            atomicExch(&g_desc[b], (inc << 2) | 1);
            int pre = 0, p = b - 1;
            while (true) {
                int d;
                do { d = atomicAdd(&g_desc[p], 0); } while (!(d & 3));
                pre += d >> 2;
                if ((d & 3) == 2) break;
                --p;
            }
            atomicExch(&g_desc[b], ((pre + inc) << 2) | 2);
            spref = pre;
        }
    }
    __syncthreads();
    int rs = sp[t] - v + spref;
    g_rowstart[idx] = rs;
    if (idx < NN) g_cursor[idx] = rs;
    g_dinv[idx] = rsqrtf((float)(v + 1));
    g_cnt[idx]  = 0;
    if (b == 0) {
        #pragma unroll
        for (int k = 0; k < 2; ++k) {
            int c = t + k * 256;
            float su = g_colsum[c], sq = g_colsq[c];
            float mu  = su * (1.f / NN);
            float var = sq * (1.f / NN) - mu * mu;
            g_mu[c]   = mu;
            g_rstd[c] = rsqrtf(var + EPSV);
            g_colsum[c] = 0.f;
            g_colsq [c] = 0.f;
        }
    }
}

// ================ kC: CSR fill + fused BinActive-pack/popc-GEMM1 ===============
__global__ void kC(const int* __restrict__ edges, const float* __restrict__ x)
{
    int b = blockIdx.x;
    int t = threadIdx.x;                 // 512
    if (b < NFB) {
        int e = b * 512 + t;
        if (e >= NE) return;
        int row = edges[e];
        int col = edges[NE + e];
        int pos = atomicAdd(&g_cursor[col], 1);
        g_esrc[pos] = row;
        return;
    }
    int lane = t & 31, wp = t >> 5;
    int m0 = (b - NFB) * 16;
    int m  = m0 + wp;

    __shared__ unsigned sA[16][16];

    if (m < NN) {
        float ab = 0.f;
        const float* xr = x + (size_t)m * FIN;
        #pragma unroll
        for (int w = 0; w < 16; ++w) {
            int c = w * 32 + lane;
            float d = __ldg(&xr[c]) - g_mu[c];
            unsigned bal = __ballot_sync(0xffffffffu, d > 0.f);
            if (lane == 0) sA[wp][w] = bal;
            ab += fabsf(d) * g_rstd[c];
        }
        #pragma unroll
        for (int o = 16; o > 0; o >>= 1) ab += __shfl_down_sync(0xffffffffu, ab, o);
        if (lane == 0) g_s1[m] = ab * (1.f / FIN) * g_dinv[m];
    } else {
        if (lane < 16) sA[wp][lane] = 0u;
    }
    __syncthreads();

    int n  = t & 127;
    int rg = t >> 7;                      // 0..3, 4 rows each
    unsigned wr[16];
    #pragma unroll
    for (int i = 0; i < 16; ++i) wr[i] = g_wp1[n * 16 + i];
    #pragma unroll
    for (int k = 0; k < 4; ++k) {
        int r = rg * 4 + k;
        int acc = 0;
        #pragma unroll
        for (int i = 0; i < 16; ++i) acc += __popc(wr[i] ^ sA[r][i]);
        float fd = (float)(FIN - 2 * acc);          // even int, exact in bf16
        g_h1b[(m0 + r) * HID + n] = __bfloat16_as_ushort(__float2bfloat16(fd));
    }
}

// ================ gather1: warp-per-node, bf16 rows, fused BinActive + GEMM2 ===
// 256 thr = 8 warps = 8 nodes per block. Lane l owns cols 4l..4l+3.
__global__ void k_gather1(const float* __restrict__ b1)
{
    int lane = threadIdx.x & 31;
    int i = blockIdx.x * 8 + (threadIdx.x >> 5);
    const uint2* rows = (const uint2*)g_h1b;

    float4 acc;
    {   // self loop
        float sr = __ldg(&g_s1[i]);
        uint2 u = __ldg(&rows[i * 32 + lane]);
        acc.x = sr * bflo(u.x);
        acc.y = sr * bfhi(u.x);
        acc.z = sr * bflo(u.y);
        acc.w = sr * bfhi(u.y);
    }
    int s = g_rowstart[i], e = g_rowstart[i + 1];
    for (int base = s; base < e; base += 32) {
        int cnt = e - base; if (cnt > 32) cnt = 32;
        int idx = 0; float sv = 0.f;
        if (lane < cnt) { idx = __ldg(&g_esrc[base + lane]); sv = __ldg(&g_s1[idx]); }
        int k = 0;
        for (; k + 1 < cnt; k += 2) {
            int   r0 = __shfl_sync(0xffffffffu, idx, k);
            int   r1 = __shfl_sync(0xffffffffu, idx, k + 1);
            float q0 = __shfl_sync(0xffffffffu, sv, k);
            float q1 = __shfl_sync(0xffffffffu, sv, k + 1);
            uint2 u0 = __ldg(&rows[r0 * 32 + lane]);
            uint2 u1 = __ldg(&rows[r1 * 32 + lane]);
            acc.x += q0 * bflo(u0.x) + q1 * bflo(u1.x);
            acc.y += q0 * bfhi(u0.x) + q1 * bfhi(u1.x);
            acc.z += q0 * bflo(u0.y) + q1 * bflo(u1.y);
            acc.w += q0 * bfhi(u0.y) + q1 * bfhi(u1.y);
        }
        if (k < cnt) {
            int   r0 = __shfl_sync(0xffffffffu, idx, k);
            float q0 = __shfl_sync(0xffffffffu, sv, k);
            uint2 u0 = __ldg(&rows[r0 * 32 + lane]);
            acc.x += q0 * bflo(u0.x);
            acc.y += q0 * bfhi(u0.x);
            acc.z += q0 * bflo(u0.y);
            acc.w += q0 * bfhi(u0.y);
        }
    }

    float di = g_dinv[i];
    float4 bb = __ldg((const float4*)&b1[lane * 4]);
    float4 be = *(const float4*)&g_beta1[lane * 4];
    float a0 = bb.x + di * be.x * acc.x;
    float a1 = bb.y + di * be.y * acc.y;
    float a2 = bb.z + di * be.z * acc.z;
    float a3 = bb.w + di * be.w * acc.w;

    float av = fabsf(a0) + fabsf(a1) + fabsf(a2) + fabsf(a3);
    #pragma unroll
    for (int o = 16; o > 0; o >>= 1) av += __shfl_xor_sync(0xffffffffu, av, o);
    if (lane == 0) g_s2[i] = av * (1.f / HID) * di;

    unsigned x0 = __ballot_sync(0xffffffffu, a0 > 0.f);
    unsigned x1 = __ballot_sync(0xffffffffu, a1 > 0.f);
    unsigned x2 = __ballot_sync(0xffffffffu, a2 > 0.f);
    unsigned x3 = __ballot_sync(0xffffffffu, a3 > 0.f);

    // lane l computes output cols 2l, 2l+1 (permuted wp2: word w bit j = sign W2[4j+w, n])
    uint4 wA = *(const uint4*)&g_wp2[(2 * lane) * 4];
    uint4 wB = *(const uint4*)&g_wp2[(2 * lane + 1) * 4];
    float d1 = (float)(HID - 2 * (__popc(wA.x ^ x0) + __popc(wA.y ^ x1)
                                + __popc(wA.z ^ x2) + __popc(wA.w ^ x3)));
    float d2 = (float)(HID - 2 * (__popc(wB.x ^ x0) + __popc(wB.y ^ x1)
                                + __popc(wB.z ^ x2) + __popc(wB.w ^ x3)));
    unsigned pk;
    asm("cvt.rn.bf16x2.f32 %0, %1, %2;" : "=r"(pk) : "f"(d2), "f"(d1)); // lo=d1, hi=d2
    g_h2b[i * 32 + lane] = pk;
}

// ================ gather2: warp-per-node, bf16 rows + fused log_softmax ========
// Lane l owns cols 2l, 2l+1.
__global__ void k_gather2_lsm(const float* __restrict__ b2, float* __restrict__ out)
{
    int lane = threadIdx.x & 31;
    int i = blockIdx.x * 8 + (threadIdx.x >> 5);
    const unsigned* rows = g_h2b;

    float2 acc;
    {
        float sr = __ldg(&g_s2[i]);
        unsigned u = __ldg(&rows[i * 32 + lane]);
        acc.x = sr * bflo(u);
        acc.y = sr * bfhi(u);
    }
    int s = g_rowstart[i], e = g_rowstart[i + 1];
    for (int base = s; base < e; base += 32) {
        int cnt = e - base; if (cnt > 32) cnt = 32;
        int idx = 0; float sv = 0.f;
        if (lane < cnt) { idx = __ldg(&g_esrc[base + lane]); sv = __ldg(&g_s2[idx]); }
        int k = 0;
        for (; k + 1 < cnt; k += 2) {
            int   r0 = __shfl_sync(0xffffffffu, idx, k);
            int   r1 = __shfl_sync(0xffffffffu, idx, k + 1);
            float q0 = __shfl_sync(0xffffffffu, sv, k);
            float q1 = __shfl_sync(0xffffffffu, sv, k + 1);
            unsigned u0 = __ldg(&rows[r0 * 32 + lane]);
            unsigned u1 = __ldg(&rows[r1 * 32 + lane]);
            acc.x += q0 * bflo(u0) + q1 * bflo(u1);
            acc.y += q0 * bfhi(u0) + q1 * bfhi(u1);
        }
        if (k < cnt) {
            int   r0 = __shfl_sync(0xffffffffu, idx, k);
            float q0 = __shfl_sync(0xffffffffu, sv, k);
            unsigned u0 = __ldg(&rows[r0 * 32 + lane]);
            acc.x += q0 * bflo(u0);
            acc.y += q0 * bfhi(u0);
        }
    }

    float di = g_dinv[i];
    float2 bb = __ldg((const float2*)&b2[lane * 2]);
    float2 be = *(const float2*)&g_beta2[lane * 2];
    float a0 = bb.x + di * be.x * acc.x;
    float a1 = bb.y + di * be.y * acc.y;

    float mx = fmaxf(a0, a1);
    #pragma unroll
    for (int o = 16; o > 0; o >>= 1) mx = fmaxf(mx, __shfl_xor_sync(0xffffffffu, mx, o));
    float sum = expf(a0 - mx) + expf(a1 - mx);
    #pragma unroll
    for (int o = 16; o > 0; o >>= 1) sum += __shfl_xor_sync(0xffffffffu, sum, o);
    float l = mx + logf(sum);
    ((float2*)out)[i * 32 + lane] = make_float2(a0 - l, a1 - l);
}

// ---------------- launch ---------------------------------------------------------
extern "C" void kernel_launch(void* const* d_in, const int* in_sizes, int n_in,
                              void* d_out, int out_size)
{
    const float* x     = (const float*)d_in[0];
    const int*   edges = (const int*)  d_in[1];
    const float* W1    = (const float*)d_in[2];
    const float* b1    = (const float*)d_in[3];
    const float* W2    = (const float*)d_in[4];
    const float* b2    = (const float*)d_in[5];
    float*       out   = (float*)d_out;

    kA<<<NFB + 400 + 192, 512>>>(edges, x, W1, W2);
    k_scan<<<NBLK, 256>>>();
    kC<<<NFB + NP / 16, 512>>>(edges, x);
    k_gather1<<<NN / 8, 256>>>(b1);
    k_gather2_lsm<<<NN / 8, 256>>>(b2, out);
}

// round 8
// speedup vs baseline: 6.6061x; 1.1795x over previous
#include <cuda_runtime.h>
#include <cuda_bf16.h>

#define NN   50000
#define NP   50176          // padded rows: multiple of 256
#define NBLK 196            // NP / 256
#define FIN  512
#define HID  128
#define CLS  64
#define NE   800000
#define EPSV 1e-5f
#define NFB  1563           // ceil(NE/512)

// ---------------- scratch (device globals) ------------------------------------
__device__ __align__(16) float    g_colsum[FIN];
__device__ __align__(16) float    g_colsq [FIN];
__device__ __align__(16) float    g_mu    [FIN];
__device__ __align__(16) float    g_rstd  [FIN];
__device__ int      g_cnt   [NP];      // zeroed each call by k_scan
__device__ float    g_dinv  [NP];
__device__ int      g_rowstart[NP];
__device__ int      g_cursor  [NN];
__device__ int      g_esrc    [NE];
__device__ int      g_desc    [NBLK];  // lookback descriptors; reset in kA

__device__ __align__(16) unsigned g_wp1 [HID * 16]; // word w bit l: k=4l+128(w>>2)+(w&3)
__device__ __align__(16) float    g_beta1[HID];
__device__ __align__(16) unsigned g_wp2 [CLS * 4];  // word w bit b: k=8(b&15)+2w+(b>>4)
__device__ __align__(16) float    g_beta2[CLS];

__device__ __align__(16) unsigned short g_h1b[NP * HID];     // bf16 counts (exact)
__device__ float    g_s1 [NP];                                // alpha1 * dinv
__device__ __align__(16) unsigned g_h2b[NP * CLS / 2];        // bf16x2 counts
__device__ float    g_s2 [NP];

__device__ __forceinline__ float bflo(unsigned w) { return __uint_as_float(w << 16); }
__device__ __forceinline__ float bfhi(unsigned w) { return __uint_as_float(w & 0xffff0000u); }

// ================ kA: cnt + colstats + pack_w (block ranges) ==================
__global__ void kA(const int* __restrict__ edges,
                   const float* __restrict__ x,
                   const float* __restrict__ W1,
                   const float* __restrict__ W2)
{
    int b = blockIdx.x;
    int t = threadIdx.x;                 // 512
    int lane = t & 31, w = t >> 5;

    if (b < NFB) {
        if (b == 0 && t < NBLK) g_desc[t] = 0;
        int e = b * 512 + t;
        if (e < NE) atomicAdd(&g_cnt[edges[NE + e]], 1);
        return;
    }
    if (b < NFB + 400) {
        int r0 = (b - NFB) * 125;
        int r1 = r0 + 125; if (r1 > NN) r1 = NN;
        float s = 0.f, q = 0.f;
        const float* xc = x + t;
        for (int r = r0; r < r1; ++r) {
            float v = __ldg(&xc[(size_t)r * FIN]);
            s += v; q += v * v;
        }
        atomicAdd(&g_colsum[t], s);
        atomicAdd(&g_colsq [t], q);
        return;
    }
    int bw = b - NFB - 400;              // 0..191
    __shared__ float ssum[16];
    if (bw < HID) {
        // permuted: word w bit lane -> k = 4*lane + 128*(w>>2) + (w&3)
        int k = 4 * lane + 128 * (w >> 2) + (w & 3);
        float v = W1[k * HID + bw];
        unsigned bal = __ballot_sync(0xffffffffu, v > 0.f);
        if (lane == 0) g_wp1[bw * 16 + w] = bal;
        float av = fabsf(v);
        #pragma unroll
        for (int o = 16; o > 0; o >>= 1) av += __shfl_down_sync(0xffffffffu, av, o);
        if (lane == 0) ssum[w] = av;
        __syncthreads();
        if (t < 16) {
            float s = ssum[t];
            #pragma unroll
            for (int o = 8; o > 0; o >>= 1) s += __shfl_down_sync(0xffffu, s, o);
            if (t == 0) g_beta1[bw] = s * (1.f / FIN);
        }
    } else {
        int n = bw - HID;
        // permuted: word w bit b -> k = 8*(b&15) + 2*w + (b>>4)
        int k = 8 * (lane & 15) + 2 * w + (lane >> 4);
        float v = (t < HID) ? W2[k * CLS + n] : 0.f;
        unsigned bal = __ballot_sync(0xffffffffu, v > 0.f);
        if (lane == 0 && w < 4) g_wp2[n * 4 + w] = bal;
        float av = fabsf(v);
        #pragma unroll
        for (int o = 16; o > 0; o >>= 1) av += __shfl_down_sync(0xffffffffu, av, o);
        if (lane == 0) ssum[w] = av;
        __syncthreads();
        if (t == 0)
            g_beta2[n] = (ssum[0] + ssum[1] + ssum[2] + ssum[3]) * (1.f / HID);
    }
}

// ================ kB: single-pass scan (decoupled lookback) + BN finalize =====
__global__ void k_scan()
{
    __shared__ int sp[256];
    __shared__ int spref;
    int t = threadIdx.x, b = blockIdx.x, idx = b * 256 + t;
    int v = g_cnt[idx];
    sp[t] = v; __syncthreads();
    #pragma unroll
    for (int off = 1; off < 256; off <<= 1) {
        int u = (t >= off) ? sp[t - off] : 0;
        __syncthreads();
        sp[t] += u;
        __syncthreads();
    }
    if (t == 255) {
        int inc = sp[255];
        if (b == 0) {
            atomicExch(&g_desc[0], (inc << 2) | 2);
            spref = 0;
        } else {
            atomicExch(&g_desc[b], (inc << 2) | 1);
            int pre = 0, p = b - 1;
            while (true) {
                int d;
                do { d = atomicAdd(&g_desc[p], 0); } while (!(d & 3));
                pre += d >> 2;
                if ((d & 3) == 2) break;
                --p;
            }
            atomicExch(&g_desc[b], ((pre + inc) << 2) | 2);
            spref = pre;
        }
    }
    __syncthreads();
    int rs = sp[t] - v + spref;
    g_rowstart[idx] = rs;
    if (idx < NN) g_cursor[idx] = rs;
    g_dinv[idx] = rsqrtf((float)(v + 1));
    g_cnt[idx]  = 0;
    if (b == 0) {
        #pragma unroll
        for (int k = 0; k < 2; ++k) {
            int c = t + k * 256;
            float su = g_colsum[c], sq = g_colsq[c];
            float mu  = su * (1.f / NN);
            float var = sq * (1.f / NN) - mu * mu;
            g_mu[c]   = mu;
            g_rstd[c] = rsqrtf(var + EPSV);
            g_colsum[c] = 0.f;
            g_colsq [c] = 0.f;
        }
    }
}

// ================ kC: CSR fill + fused BinActive-pack/popc-GEMM1 ===============
__global__ void kC(const int* __restrict__ edges, const float* __restrict__ x)
{
    int b = blockIdx.x;
    int t = threadIdx.x;                 // 512
    if (b < NFB) {
        int e = b * 512 + t;
        if (e >= NE) return;
        int row = edges[e];
        int col = edges[NE + e];
        int pos = atomicAdd(&g_cursor[col], 1);
        g_esrc[pos] = row;
        return;
    }
    int lane = t & 31, wp = t >> 5;
    int m0 = (b - NFB) * 16;
    int m  = m0 + wp;

    __shared__ unsigned sA[16][16];

    if (m < NN) {
        float ab = 0.f;
        const float4* xr4 = (const float4*)(x + (size_t)m * FIN);
        #pragma unroll
        for (int s = 0; s < 4; ++s) {
            float4 xv  = __ldg(&xr4[lane + 32 * s]);
            float4 muv = *(const float4*)&g_mu  [4 * lane + 128 * s];
            float4 rsv = *(const float4*)&g_rstd[4 * lane + 128 * s];
            float d0 = xv.x - muv.x, d1 = xv.y - muv.y;
            float d2 = xv.z - muv.z, d3 = xv.w - muv.w;
            unsigned b0 = __ballot_sync(0xffffffffu, d0 > 0.f);
            unsigned b1 = __ballot_sync(0xffffffffu, d1 > 0.f);
            unsigned b2 = __ballot_sync(0xffffffffu, d2 > 0.f);
            unsigned b3 = __ballot_sync(0xffffffffu, d3 > 0.f);
            if (lane == 0) {
                sA[wp][4 * s + 0] = b0; sA[wp][4 * s + 1] = b1;
                sA[wp][4 * s + 2] = b2; sA[wp][4 * s + 3] = b3;
            }
            ab += fabsf(d0) * rsv.x + fabsf(d1) * rsv.y
                + fabsf(d2) * rsv.z + fabsf(d3) * rsv.w;
        }
        #pragma unroll
        for (int o = 16; o > 0; o >>= 1) ab += __shfl_down_sync(0xffffffffu, ab, o);
        if (lane == 0) g_s1[m] = ab * (1.f / FIN) * g_dinv[m];
    } else {
        if (lane < 16) sA[wp][lane] = 0u;
    }
    __syncthreads();

    int n  = t & 127;
    int rg = t >> 7;                      // 0..3, 4 rows each
    unsigned wr[16];
    #pragma unroll
    for (int i = 0; i < 16; ++i) wr[i] = g_wp1[n * 16 + i];
    #pragma unroll
    for (int k = 0; k < 4; ++k) {
        int r = rg * 4 + k;
        int acc = 0;
        #pragma unroll
        for (int i = 0; i < 16; ++i) acc += __popc(wr[i] ^ sA[r][i]);
        float fd = (float)(FIN - 2 * acc);          // even int, exact in bf16
        g_h1b[(m0 + r) * HID + n] = __bfloat16_as_ushort(__float2bfloat16(fd));
    }
}

// ================ gather1: 2 edges/warp (half-warps), fused BinActive + GEMM2 ==
// 256 thr = 8 warps = 8 nodes/block. Lane: half = lane>>4, m16 = lane&15.
// Lane covers cols 8*m16 .. 8*m16+7 via one uint4 (8 bf16).
__global__ void k_gather1(const float* __restrict__ b1)
{
    int lane = threadIdx.x & 31;
    int i = blockIdx.x * 8 + (threadIdx.x >> 5);
    int half = lane >> 4, m16 = lane & 15;
    const uint4* rows = (const uint4*)g_h1b;   // row r = rows[r*16 + m16]

    float a0, a1, a2, a3, a4, a5, a6, a7;
    {   // self loop: lower half only
        float sr = half ? 0.f : __ldg(&g_s1[i]);
        uint4 u = __ldg(&rows[i * 16 + m16]);
        a0 = sr * bflo(u.x); a1 = sr * bfhi(u.x);
        a2 = sr * bflo(u.y); a3 = sr * bfhi(u.y);
        a4 = sr * bflo(u.z); a5 = sr * bfhi(u.z);
        a6 = sr * bflo(u.w); a7 = sr * bfhi(u.w);
    }
    int s = g_rowstart[i], e = g_rowstart[i + 1];
    for (int base = s; base < e; base += 32) {
        int cnt = e - base; if (cnt > 32) cnt = 32;
        int idx = 0; float sv = 0.f;
        if (lane < cnt) { idx = __ldg(&g_esrc[base + lane]); sv = __ldg(&g_s1[idx]); }
        for (int k = 0; k < cnt; k += 4) {       // 4 edges per iteration
            int kk0 = k + half, kk1 = k + 2 + half;      // both <= 31
            int   r0 = __shfl_sync(0xffffffffu, idx, kk0);
            float q0 = __shfl_sync(0xffffffffu, sv,  kk0);
            int   r1 = __shfl_sync(0xffffffffu, idx, kk1);
            float q1 = __shfl_sync(0xffffffffu, sv,  kk1);
            uint4 u0 = __ldg(&rows[r0 * 16 + m16]);
            uint4 u1 = __ldg(&rows[r1 * 16 + m16]);
            a0 += q0 * bflo(u0.x) + q1 * bflo(u1.x);
            a1 += q0 * bfhi(u0.x) + q1 * bfhi(u1.x);
            a2 += q0 * bflo(u0.y) + q1 * bflo(u1.y);
            a3 += q0 * bfhi(u0.y) + q1 * bfhi(u1.y);
            a4 += q0 * bflo(u0.z) + q1 * bflo(u1.z);
            a5 += q0 * bfhi(u0.z) + q1 * bfhi(u1.z);
            a6 += q0 * bflo(u0.w) + q1 * bflo(u1.w);
            a7 += q0 * bfhi(u0.w) + q1 * bfhi(u1.w);
        }
    }
    // combine half-warps
    a0 += __shfl_xor_sync(0xffffffffu, a0, 16);
    a1 += __shfl_xor_sync(0xffffffffu, a1, 16);
    a2 += __shfl_xor_sync(0xffffffffu, a2, 16);
    a3 += __shfl_xor_sync(0xffffffffu, a3, 16);
    a4 += __shfl_xor_sync(0xffffffffu, a4, 16);
    a5 += __shfl_xor_sync(0xffffffffu, a5, 16);
    a6 += __shfl_xor_sync(0xffffffffu, a6, 16);
    a7 += __shfl_xor_sync(0xffffffffu, a7, 16);

    float di = g_dinv[i];
    float4 bbA = __ldg((const float4*)&b1[8 * m16]);
    float4 bbB = __ldg((const float4*)&b1[8 * m16 + 4]);
    float4 beA = *(const float4*)&g_beta1[8 * m16];
    float4 beB = *(const float4*)&g_beta1[8 * m16 + 4];
    a0 = bbA.x + di * beA.x * a0;  a1 = bbA.y + di * beA.y * a1;
    a2 = bbA.z + di * beA.z * a2;  a3 = bbA.w + di * beA.w * a3;
    a4 = bbB.x + di * beB.x * a4;  a5 = bbB.y + di * beB.y * a5;
    a6 = bbB.z + di * beB.z * a6;  a7 = bbB.w + di * beB.w * a7;

    float av = fabsf(a0) + fabsf(a1) + fabsf(a2) + fabsf(a3)
             + fabsf(a4) + fabsf(a5) + fabsf(a6) + fabsf(a7);
    #pragma unroll
    for (int o = 8; o > 0; o >>= 1) av += __shfl_xor_sync(0xffffffffu, av, o);
    if (lane == 0) g_s2[i] = av * (1.f / HID) * di;

    // ballots: bal_j bit l = sign(a_j at lane l); col = 8*(l&15) + j (halves dup)
    unsigned bal0 = __ballot_sync(0xffffffffu, a0 > 0.f);
    unsigned bal1 = __ballot_sync(0xffffffffu, a1 > 0.f);
    unsigned bal2 = __ballot_sync(0xffffffffu, a2 > 0.f);
    unsigned bal3 = __ballot_sync(0xffffffffu, a3 > 0.f);
    unsigned bal4 = __ballot_sync(0xffffffffu, a4 > 0.f);
    unsigned bal5 = __ballot_sync(0xffffffffu, a5 > 0.f);
    unsigned bal6 = __ballot_sync(0xffffffffu, a6 > 0.f);
    unsigned bal7 = __ballot_sync(0xffffffffu, a7 > 0.f);
    unsigned x0 = (bal0 & 0xffffu) | (bal1 << 16);
    unsigned x1 = (bal2 & 0xffffu) | (bal3 << 16);
    unsigned x2 = (bal4 & 0xffffu) | (bal5 << 16);
    unsigned x3 = (bal6 & 0xffffu) | (bal7 << 16);

    // lane l -> output cols 2l, 2l+1 (wp2 packed in matching bit order)
    uint4 wA = *(const uint4*)&g_wp2[(2 * lane) * 4];
    uint4 wB = *(const uint4*)&g_wp2[(2 * lane + 1) * 4];
    float d1 = (float)(HID - 2 * (__popc(wA.x ^ x0) + __popc(wA.y ^ x1)
                                + __popc(wA.z ^ x2) + __popc(wA.w ^ x3)));
    float d2 = (float)(HID - 2 * (__popc(wB.x ^ x0) + __popc(wB.y ^ x1)
                                + __popc(wB.z ^ x2) + __popc(wB.w ^ x3)));
    unsigned pk;
    asm("cvt.rn.bf16x2.f32 %0, %1, %2;" : "=r"(pk) : "f"(d2), "f"(d1)); // lo=d1, hi=d2
    g_h2b[i * 32 + lane] = pk;
}

// ================ gather2: 4 edges/warp (8-lane groups) + fused log_softmax ====
// Lane: grp = lane>>3, j8 = lane&7. Lane covers cols 8*j8 .. 8*j8+7 (4 bf16x2).
__global__ void k_gather2_lsm(const float* __restrict__ b2, float* __restrict__ out)
{
    int lane = threadIdx.x & 31;
    int i = blockIdx.x * 8 + (threadIdx.x >> 5);
    int grp = lane >> 3, j8 = lane & 7;
    const uint4* rows = (const uint4*)g_h2b;   // row r = rows[r*8 + j8]

    float a0, a1, a2, a3, a4, a5, a6, a7;
    {   // self loop: group 0 only
        float sr = grp ? 0.f : __ldg(&g_s2[i]);
        uint4 u = __ldg(&rows[i * 8 + j8]);
        a0 = sr * bflo(u.x); a1 = sr * bfhi(u.x);
        a2 = sr * bflo(u.y); a3 = sr * bfhi(u.y);
        a4 = sr * bflo(u.z); a5 = sr * bfhi(u.z);
        a6 = sr * bflo(u.w); a7 = sr * bfhi(u.w);
    }
    int s = g_rowstart[i], e = g_rowstart[i + 1];
    for (int base = s; base < e; base += 32) {
        int cnt = e - base; if (cnt > 32) cnt = 32;
        int idx = 0; float sv = 0.f;
        if (lane < cnt) { idx = __ldg(&g_esrc[base + lane]); sv = __ldg(&g_s2[idx]); }
        for (int k = 0; k < cnt; k += 8) {        // 8 edges per iteration
            int kk0 = k + grp, kk1 = k + 4 + grp;       // both <= 31
            int   r0 = __shfl_sync(0xffffffffu, idx, kk0);
            float q0 = __shfl_sync(0xffffffffu, sv,  kk0);
            int   r1 = __shfl_sync(0xffffffffu, idx, kk1);
            float q1 = __shfl_sync(0xffffffffu, sv,  kk1);
            uint4 u0 = __ldg(&rows[r0 * 8 + j8]);
            uint4 u1 = __ldg(&rows[r1 * 8 + j8]);
            a0 += q0 * bflo(u0.x) + q1 * bflo(u1.x);
            a1 += q0 * bfhi(u0.x) + q1 * bfhi(u1.x);
            a2 += q0 * bflo(u0.y) + q1 * bflo(u1.y);
            a3 += q0 * bfhi(u0.y) + q1 * bfhi(u1.y);
            a4 += q0 * bflo(u0.z) + q1 * bflo(u1.z);
            a5 += q0 * bfhi(u0.z) + q1 * bfhi(u1.z);
            a6 += q0 * bflo(u0.w) + q1 * bflo(u1.w);
            a7 += q0 * bfhi(u0.w) + q1 * bfhi(u1.w);
        }
    }
    // combine the 4 groups
    #pragma unroll
    for (int o = 8; o <= 16; o <<= 1) {
        a0 += __shfl_xor_sync(0xffffffffu, a0, o);
        a1 += __shfl_xor_sync(0xffffffffu, a1, o);
        a2 += __shfl_xor_sync(0xffffffffu, a2, o);
        a3 += __shfl_xor_sync(0xffffffffu, a3, o);
        a4 += __shfl_xor_sync(0xffffffffu, a4, o);
        a5 += __shfl_xor_sync(0xffffffffu, a5, o);
        a6 += __shfl_xor_sync(0xffffffffu, a6, o);
        a7 += __shfl_xor_sync(0xffffffffu, a7, o);
    }

    float di = g_dinv[i];
    float4 bbA = __ldg((const float4*)&b2[8 * j8]);
    float4 bbB = __ldg((const float4*)&b2[8 * j8 + 4]);
    float4 beA = *(const float4*)&g_beta2[8 * j8];
    float4 beB = *(const float4*)&g_beta2[8 * j8 + 4];
    a0 = bbA.x + di * beA.x * a0;  a1 = bbA.y + di * beA.y * a1;
    a2 = bbA.z + di * beA.z * a2;  a3 = bbA.w + di * beA.w * a3;
    a4 = bbB.x + di * beB.x * a4;  a5 = bbB.y + di * beB.y * a5;
    a6 = bbB.z + di * beB.z * a6;  a7 = bbB.w + di * beB.w * a7;

    float mx = fmaxf(fmaxf(fmaxf(a0, a1), fmaxf(a2, a3)),
                     fmaxf(fmaxf(a4, a5), fmaxf(a6, a7)));
    #pragma unroll
    for (int o = 4; o > 0; o >>= 1) mx = fmaxf(mx, __shfl_xor_sync(0xffffffffu, mx, o));
    float sum = expf(a0 - mx) + expf(a1 - mx) + expf(a2 - mx) + expf(a3 - mx)
              + expf(a4 - mx) + expf(a5 - mx) + expf(a6 - mx) + expf(a7 - mx);
    #pragma unroll
    for (int o = 4; o > 0; o >>= 1) sum += __shfl_xor_sync(0xffffffffu, sum, o);
    float l = mx + logf(sum);

    if (grp == 0) {
        float4* o4 = (float4*)(out + (size_t)i * CLS + 8 * j8);
        o4[0] = make_float4(a0 - l, a1 - l, a2 - l, a3 - l);
        o4[1] = make_float4(a4 - l, a5 - l, a6 - l, a7 - l);
    }
}

// ---------------- launch ---------------------------------------------------------
extern "C" void kernel_launch(void* const* d_in, const int* in_sizes, int n_in,
                              void* d_out, int out_size)
{
    const float* x     = (const float*)d_in[0];
    const int*   edges = (const int*)  d_in[1];
    const float* W1    = (const float*)d_in[2];
    const float* b1    = (const float*)d_in[3];
    const float* W2    = (const float*)d_in[4];
    const float* b2    = (const float*)d_in[5];
    float*       out   = (float*)d_out;

    kA<<<NFB + 400 + 192, 512>>>(edges, x, W1, W2);
    k_scan<<<NBLK, 256>>>();
    kC<<<NFB + NP / 16, 512>>>(edges, x);
    k_gather1<<<NN / 8, 256>>>(b1);
    k_gather2_lsm<<<NN / 8, 256>>>(b2, out);
}